// round 2
// baseline (speedup 1.0000x reference)
#include <cuda_runtime.h>
#include <math.h>

// Problem constants: B=16, T=4, C=2048, n_head=16, n_kv=4, d_head=128,
// S_cache=4096, window=2048, sink=4 -> 2052 effective keys.
// Key s in [0,2052): s<4 -> cache row s ; 4<=s<2048 -> cache row s+2048 ;
// s>=2048 -> new token s-2048.

#define KSPLIT 8
#define NSPLITS 9   // 8 splits x 256 cached keys + 1 split of 4 new keys

// Scratch (no allocations allowed)
__device__ float g_qkv_part[KSPLIT][64][3072];
__device__ float g_q[64 * 2048];
__device__ float g_k[64 * 512];
__device__ float g_v[64 * 512];
__device__ float g_po[64 * NSPLITS * 16 * 128];
__device__ float g_pm[64 * NSPLITS * 16];
__device__ float g_pl[64 * NSPLITS * 16];
__device__ float g_y[64 * 2048];
__device__ float g_out_part[KSPLIT][64][2048];
__device__ float g_cos[4][64];
__device__ float g_sin[4][64];

// ------------- packed f32x2 helpers -------------
__device__ __forceinline__ void fma2(unsigned long long& d,
                                     unsigned long long a,
                                     unsigned long long b) {
    asm("fma.rn.f32x2 %0, %1, %2, %0;" : "+l"(d) : "l"(a), "l"(b));
}
__device__ __forceinline__ unsigned long long pack2(float x, float y) {
    unsigned long long r;
    asm("mov.b64 %0, {%1, %2};" : "=l"(r) : "f"(x), "f"(y));
    return r;
}
__device__ __forceinline__ float2 unpack2(unsigned long long v) {
    float2 r;
    asm("mov.b64 {%0, %1}, %2;" : "=f"(r.x), "=f"(r.y) : "l"(v));
    return r;
}

// ---------------------------------------------------------------------------
// RoPE trig tables: 4 positions x 64 freqs, fp64 for accuracy (tiny).
// ---------------------------------------------------------------------------
__global__ void rope_table_kernel(const int* __restrict__ sp) {
    int tid = blockIdx.x * 32 + threadIdx.x;   // 0..255
    if (tid >= 256) return;
    int t = tid >> 6, i = tid & 63;
    double f = exp2(-(double)i * (13.287712379549449 / 64.0)); // 10000^(-i/64)
    double ang = (double)(sp[0] + t) * f;
    double s, c;
    sincos(ang, &s, &c);
    g_cos[t][i] = (float)c;
    g_sin[t][i] = (float)s;
}

// ---------------------------------------------------------------------------
// GEMM partial: P[ks-slice] = X[64, kchunk] @ W[kchunk, 64-col tile]
// 256 threads; thread tile 4 tokens x 4 cols; packed FMA over column pairs.
// ---------------------------------------------------------------------------
__global__ void gemm64(const float* __restrict__ X, const float* __restrict__ W,
                       float* __restrict__ P, int K, int Wn, int Pn, int coff) {
    const int tid = threadIdx.x;
    const int ctile = blockIdx.x, ks = blockIdx.y;
    const int kchunk = K / KSPLIT;
    const int k0 = ks * kchunk;
    const int cbase = ctile * 64;
    __shared__ float xs[64][33];
    __shared__ float ws[32][64];
    const int tx = tid & 15, ty = tid >> 4;
    const int c = tx * 4, t0 = ty * 4;

    unsigned long long acc[4][2];
#pragma unroll
    for (int i = 0; i < 4; i++) { acc[i][0] = 0ULL; acc[i][1] = 0ULL; }

    for (int kt = k0; kt < k0 + kchunk; kt += 32) {
#pragma unroll
        for (int i = 0; i < 8; i++) {
            int idx = tid + i * 256;
            int t = idx >> 5, kk = idx & 31;
            xs[t][kk] = X[t * K + kt + kk];
        }
#pragma unroll
        for (int i = 0; i < 8; i++) {
            int idx = tid + i * 256;
            int kk = idx >> 6, cc = idx & 63;
            ws[kk][cc] = W[(size_t)(kt + kk) * Wn + cbase + cc];
        }
        __syncthreads();
#pragma unroll 8
        for (int kk = 0; kk < 32; kk++) {
            ulonglong2 w2 = *(const ulonglong2*)&ws[kk][c];
#pragma unroll
            for (int i = 0; i < 4; i++) {
                float xv = xs[t0 + i][kk];
                unsigned long long x2 = pack2(xv, xv);
                fma2(acc[i][0], x2, w2.x);
                fma2(acc[i][1], x2, w2.y);
            }
        }
        __syncthreads();
    }
#pragma unroll
    for (int i = 0; i < 4; i++) {
        float2 lo = unpack2(acc[i][0]);
        float2 hi = unpack2(acc[i][1]);
        float4 v4 = make_float4(lo.x, lo.y, hi.x, hi.y);
        *(float4*)(P + ((size_t)ks * 64 + (t0 + i)) * Pn + coff + cbase + c) = v4;
    }
}

// ---------------------------------------------------------------------------
// Reduce K-split QKV partials + fused RoPE -> g_q, g_k, g_v
// per token: 1024 q-pairs, 256 k-pairs, 256 v-pairs (r in [0,1536))
// ---------------------------------------------------------------------------
__global__ void reduce_rope_kernel() {
    int gid = blockIdx.x * 256 + threadIdx.x;
    if (gid >= 64 * 1536) return;
    int token = gid / 1536;
    int r = gid - token * 1536;
    int t = token & 3;
    const float* P = &g_qkv_part[0][0][0];

    int h, i, c1;
    bool is_q = (r < 1024), is_k = (!is_q && r < 1280);
    if (is_q)      { h = r >> 6;              i = r & 63; c1 = h * 128 + i; }
    else if (is_k) { int rr = r - 1024; h = rr >> 6; i = rr & 63; c1 = 2048 + h * 128 + i; }
    else           { int rr = r - 1280; h = rr >> 6; i = rr & 63; c1 = 2560 + h * 128 + i; }

    float s1 = 0.f, s2 = 0.f;
#pragma unroll
    for (int ks = 0; ks < KSPLIT; ks++) {
        const float* row = P + ((size_t)ks * 64 + token) * 3072;
        s1 += row[c1];
        s2 += row[c1 + 64];
    }
    if (!is_q && !is_k) {
        g_v[token * 512 + h * 128 + i] = s1;
        g_v[token * 512 + h * 128 + i + 64] = s2;
        return;
    }
    float cs = g_cos[t][i], sn = g_sin[t][i];
    float o1 = s1 * cs - s2 * sn;
    float o2 = s1 * sn + s2 * cs;
    if (is_q) {
        g_q[token * 2048 + c1] = o1;
        g_q[token * 2048 + c1 + 64] = o2;
    } else {
        int cc = h * 128 + i;
        g_k[token * 512 + cc] = o1;
        g_k[token * 512 + cc + 64] = o2;
    }
}

// ---------------------------------------------------------------------------
// Attention (flash-decoding): CTA = (pair=b*4+kvh, split).
// Pass1 scores with K stored transposed (XOR-pair swizzle, conflict-free LDS),
// per-warp softmax, Pass2 A@V row-major, packed FMA throughout.
// smem: q[16*132] + kv[8448] + at[16*260] + m[16] + l[16] = 14752 floats
// ---------------------------------------------------------------------------
#define ATTN_SMEM_BYTES (14752 * 4)

__global__ void attn_kernel(const float* __restrict__ ck,
                            const float* __restrict__ cv) {
    extern __shared__ float sm[];
    float* q_s  = sm;               // [16][132]
    float* kv_s = sm + 16 * 132;    // kt: transposed K (8192) OR v [64][132]
    float* at_s = kv_s + 8448;      // [16][260]
    float* m_s  = at_s + 16 * 260;
    float* l_s  = m_s + 16;

    const int tid = threadIdx.x;
    const int bidx = blockIdx.x;
    const int split = bidx % NSPLITS;
    const int pair = bidx / NSPLITS;
    const int b = pair >> 2, kvh = pair & 3;
    const int len = (split < 8) ? 256 : 4;
    const int NT  = (split < 8) ? 4 : 1;

    // stage Q [16 rows x 128]
#pragma unroll
    for (int i = 0; i < 8; i++) {
        int idx = tid + i * 256;
        int qi = idx >> 7, d = idx & 127;
        int hg = qi >> 2, t = qi & 3;
        q_s[qi * 132 + d] = g_q[(b * 4 + t) * 2048 + (kvh * 4 + hg) * 128 + d];
    }

    const int qg = tid >> 5;   // 0..7 (warp id)
    const int kg = tid & 31;   // lane
    const float scale = 0.08838834764831845f;

    // ---- Pass 1: scores ----
    for (int tile = 0; tile < NT; tile++) {
        __syncthreads();
        // stage K tile transposed: element (d,row) at kt[d*64 + ((row>>1 ^ (d&31))<<1) + (row&1)]
#pragma unroll
        for (int i = 0; i < 8; i++) {
            int idx = tid + i * 256;
            int row = idx >> 5, c4 = idx & 31;
            int sl = tile * 64 + row;
            const float* src;
            if (split < 8) {
                int se = split * 256 + sl;
                int crow = (se < 4) ? se : se + 2048;
                src = ck + ((size_t)(b * 4 + kvh) * 4096 + crow) * 128;
            } else {
                int t = (sl < 4) ? sl : 0;
                src = g_k + (b * 4 + t) * 512 + kvh * 128;
            }
            float4 val = ((const float4*)src)[c4];
            int d0 = c4 * 4;
            int p = row >> 1, rb = row & 1;
            kv_s[((d0 + 0) << 6) + ((p ^ ((d0 + 0) & 31)) << 1) + rb] = val.x;
            kv_s[((d0 + 1) << 6) + ((p ^ ((d0 + 1) & 31)) << 1) + rb] = val.y;
            kv_s[((d0 + 2) << 6) + ((p ^ ((d0 + 2) & 31)) << 1) + rb] = val.z;
            kv_s[((d0 + 3) << 6) + ((p ^ ((d0 + 3) & 31)) << 1) + rb] = val.w;
        }
        __syncthreads();

        // thread: q rows 2qg, 2qg+1  x  key pair (2kg, 2kg+1)
        unsigned long long a0 = 0ULL, a1 = 0ULL;
        const float* qr0 = q_s + (qg * 2) * 132;
        const float* qr1 = qr0 + 132;
#pragma unroll 8
        for (int dd = 0; dd < 128; dd++) {
            unsigned long long kv2 =
                *(const unsigned long long*)(kv_s + (dd << 6) + ((kg ^ (dd & 31)) << 1));
            fma2(a0, pack2(qr0[dd], qr0[dd]), kv2);
            fma2(a1, pack2(qr1[dd], qr1[dd]), kv2);
        }
        float2 s0 = unpack2(a0), s1 = unpack2(a1);
        int kcol = tile * 64 + kg * 2;
        at_s[(qg * 2) * 260 + kcol]         = s0.x * scale;
        at_s[(qg * 2) * 260 + kcol + 1]     = s0.y * scale;
        at_s[(qg * 2 + 1) * 260 + kcol]     = s1.x * scale;
        at_s[(qg * 2 + 1) * 260 + kcol + 1] = s1.y * scale;
    }
    __syncthreads();

    // ---- softmax: warp w owns rows 2w, 2w+1 ----
    {
        int w = qg, lane = kg;
#pragma unroll
        for (int rr = 0; rr < 2; rr++) {
            int r = w * 2 + rr;
            float* row = at_s + r * 260;
            float m = -3.0e38f;
            for (int s = lane; s < len; s += 32) m = fmaxf(m, row[s]);
#pragma unroll
            for (int off = 16; off; off >>= 1)
                m = fmaxf(m, __shfl_xor_sync(0xffffffffu, m, off));
            float l = 0.f;
            for (int s = lane; s < len; s += 32) {
                float e = __expf(row[s] - m);
                row[s] = e;
                l += e;
            }
#pragma unroll
            for (int off = 16; off; off >>= 1)
                l += __shfl_xor_sync(0xffffffffu, l, off);
            if (lane == 0) { m_s[r] = m; l_s[r] = l; }
        }
    }

    // ---- Pass 2: O = P @ V  (thread: q rows 2qg,2qg+1 ; d cols 4kg..4kg+3) ----
    unsigned long long b00 = 0ULL, b01 = 0ULL, b10 = 0ULL, b11 = 0ULL;
    for (int tile = 0; tile < NT; tile++) {
        __syncthreads();
#pragma unroll
        for (int i = 0; i < 8; i++) {
            int idx = tid + i * 256;
            int row = idx >> 5, c4 = idx & 31;
            int sl = tile * 64 + row;
            const float* src;
            if (split < 8) {
                int se = split * 256 + sl;
                int crow = (se < 4) ? se : se + 2048;
                src = cv + ((size_t)(b * 4 + kvh) * 4096 + crow) * 128;
            } else {
                int t = (sl < 4) ? sl : 0;
                src = g_v + (b * 4 + t) * 512 + kvh * 128;
            }
            *(float4*)(kv_s + row * 132 + c4 * 4) = ((const float4*)src)[c4];
        }
        __syncthreads();

        int sbound = len - tile * 64;
        if (sbound > 64) sbound = 64;
        const float* p0r = at_s + (qg * 2) * 260 + tile * 64;
        const float* p1r = p0r + 260;
        for (int s = 0; s < sbound; s++) {
            ulonglong2 v2 = *(const ulonglong2*)(kv_s + s * 132 + kg * 4);
            unsigned long long pp0 = pack2(p0r[s], p0r[s]);
            unsigned long long pp1 = pack2(p1r[s], p1r[s]);
            fma2(b00, pp0, v2.x); fma2(b01, pp0, v2.y);
            fma2(b10, pp1, v2.x); fma2(b11, pp1, v2.y);
        }
    }

    // write partials (unnormalized) + stats
    {
        size_t base = ((size_t)(pair * NSPLITS + split) * 16);
        float2 f0 = unpack2(b00), f1 = unpack2(b01);
        *(float4*)(g_po + (base + qg * 2) * 128 + kg * 4) =
            make_float4(f0.x, f0.y, f1.x, f1.y);
        float2 g0 = unpack2(b10), g1 = unpack2(b11);
        *(float4*)(g_po + (base + qg * 2 + 1) * 128 + kg * 4) =
            make_float4(g0.x, g0.y, g1.x, g1.y);
        __syncthreads();
        if (tid < 16) {
            g_pm[base + tid] = m_s[tid];
            g_pl[base + tid] = l_s[tid];
        }
    }
}

// ---------------------------------------------------------------------------
// Combine split partials -> g_y.  block = (pair*16+q), thread = d.
// ---------------------------------------------------------------------------
__global__ void combine_kernel() {
    int bidx = blockIdx.x;
    int pair = bidx >> 4, q = bidx & 15;
    int d = threadIdx.x;
    int hg = q >> 2, t = q & 3;
    int b = pair >> 2, kvh = pair & 3;

    float ms[NSPLITS];
    float M = -3.0e38f;
#pragma unroll
    for (int i = 0; i < NSPLITS; i++) {
        ms[i] = g_pm[(pair * NSPLITS + i) * 16 + q];
        M = fmaxf(M, ms[i]);
    }
    float L = 0.f, acc = 0.f;
#pragma unroll
    for (int i = 0; i < NSPLITS; i++) {
        float w = __expf(ms[i] - M);
        L += w * g_pl[(pair * NSPLITS + i) * 16 + q];
        acc += w * g_po[((size_t)(pair * NSPLITS + i) * 16 + q) * 128 + d];
    }
    g_y[(b * 4 + t) * 2048 + (kvh * 4 + hg) * 128 + d] = acc / L;
}

// ---------------------------------------------------------------------------
// Sum K-split partials of the output projection -> d_out
// ---------------------------------------------------------------------------
__global__ void reduce_out_kernel(float* __restrict__ out) {
    int gid = blockIdx.x * 256 + threadIdx.x;
    if (gid >= 64 * 2048) return;
    const float* P = &g_out_part[0][0][0];
    float s = 0.f;
#pragma unroll
    for (int ks = 0; ks < KSPLIT; ks++) s += P[(size_t)ks * 64 * 2048 + gid];
    out[gid] = s;
}

// ---------------------------------------------------------------------------
extern "C" void kernel_launch(void* const* d_in, const int* in_sizes, int n_in,
                              void* d_out, int out_size) {
    const float* x     = (const float*)d_in[0];
    const float* ck    = (const float*)d_in[1];
    const float* cv    = (const float*)d_in[2];
    const float* wq    = (const float*)d_in[3];
    const float* wk    = (const float*)d_in[4];
    const float* wv    = (const float*)d_in[5];
    const float* wproj = (const float*)d_in[6];
    const int*   sp    = (const int*)d_in[7];
    float* out = (float*)d_out;

    float *qkvp, *yp, *outp;
    cudaGetSymbolAddress((void**)&qkvp, g_qkv_part);
    cudaGetSymbolAddress((void**)&yp, g_y);
    cudaGetSymbolAddress((void**)&outp, g_out_part);

    cudaFuncSetAttribute(attn_kernel,
                         cudaFuncAttributeMaxDynamicSharedMemorySize,
                         ATTN_SMEM_BYTES);

    rope_table_kernel<<<8, 32>>>(sp);
    gemm64<<<dim3(32, KSPLIT), 256>>>(x, wq, qkvp, 2048, 2048, 3072, 0);
    gemm64<<<dim3(8,  KSPLIT), 256>>>(x, wk, qkvp, 2048, 512, 3072, 2048);
    gemm64<<<dim3(8,  KSPLIT), 256>>>(x, wv, qkvp, 2048, 512, 3072, 2560);
    reduce_rope_kernel<<<384, 256>>>();
    attn_kernel<<<64 * NSPLITS, 256, ATTN_SMEM_BYTES>>>(ck, cv);
    combine_kernel<<<1024, 128>>>();
    gemm64<<<dim3(32, KSPLIT), 256>>>(yp, wproj, outp, 2048, 2048, 2048, 0);
    reduce_out_kernel<<<512, 256>>>(out);
}

// round 3
// speedup vs baseline: 1.2043x; 1.2043x over previous
#include <cuda_runtime.h>
#include <math.h>

// B=16, T=4, C=2048, 16 heads / 4 kv heads, d=128, S_cache=4096,
// window=2048, sink=4 -> 2052 effective keys.
// Key s: s<4 -> cache row s ; 4<=s<2048 -> cache row s+2048 ; s>=2048 -> new.

#define KSPLIT 16
#define NSPLITS 9   // 8 x 256 cached keys + 1 x 4 new keys

__device__ float g_qkv_part[KSPLIT][64][3072];
__device__ float g_q[64 * 2048];
__device__ float g_k[64 * 512];
__device__ float g_v[64 * 512];
__device__ float g_po[64 * NSPLITS * 16 * 128];
__device__ float g_pm[64 * NSPLITS * 16];
__device__ float g_pl[64 * NSPLITS * 16];
__device__ float g_y[64 * 2048];
__device__ float g_out_part[KSPLIT][64][2048];
__device__ float g_cos[4][64];
__device__ float g_sin[4][64];

typedef unsigned long long ull;

__device__ __forceinline__ void fma2(ull& d, ull a, ull b) {
    asm("fma.rn.f32x2 %0, %1, %2, %0;" : "+l"(d) : "l"(a), "l"(b));
}
__device__ __forceinline__ ull pack2(float x, float y) {
    ull r;
    asm("mov.b64 %0, {%1, %2};" : "=l"(r) : "f"(x), "f"(y));
    return r;
}
__device__ __forceinline__ float2 unpack2(ull v) {
    float2 r;
    asm("mov.b64 {%0, %1}, %2;" : "=f"(r.x), "=f"(r.y) : "l"(v));
    return r;
}

// ---------------------------------------------------------------------------
// RoPE trig tables (tiny, fp64 for accuracy)
// ---------------------------------------------------------------------------
__global__ void rope_table_kernel(const int* __restrict__ sp) {
    int tid = blockIdx.x * 32 + threadIdx.x;
    if (tid >= 256) return;
    int t = tid >> 6, i = tid & 63;
    double f = exp2(-(double)i * (13.287712379549449 / 64.0));
    double ang = (double)(sp[0] + t) * f;
    double s, c;
    sincos(ang, &s, &c);
    g_cos[t][i] = (float)c;
    g_sin[t][i] = (float)s;
}

// ---------------------------------------------------------------------------
// Big GEMM: 64 tokens x 128-col tile, K-chunk 128 (ksplit 16).
// qkv=1: fused QKV (ctile 0-15 wq, 16-19 wk, 20-23 wv). qkv=0: wa only.
// X pre-splatted in smem -> inner loop has zero pack instructions.
// ---------------------------------------------------------------------------
__global__ void gemm_big(const float* __restrict__ X,
                         const float* __restrict__ wa,
                         const float* __restrict__ wb,
                         const float* __restrict__ wc,
                         float* __restrict__ P, int Pn, int qkv) {
    const int tid = threadIdx.x;
    const int ct = blockIdx.x, ks = blockIdx.y;
    const float* W;
    int Wn, Wc, ob;
    if (qkv) {
        if (ct < 16)      { W = wa; Wn = 2048; Wc = ct * 128;        ob = Wc; }
        else if (ct < 20) { W = wb; Wn = 512;  Wc = (ct - 16) * 128; ob = 2048 + Wc; }
        else              { W = wc; Wn = 512;  Wc = (ct - 20) * 128; ob = 2560 + Wc; }
    } else { W = wa; Wn = 2048; Wc = ct * 128; ob = Wc; }
    const int k0 = ks * 128;

    __shared__ float xs[64 * 68];    // splatted pairs: [tok][kk] as (x,x)
    __shared__ float ws[32 * 132];   // [kk][128 cols]

    const int tx = tid & 15, ty = tid >> 4;
    ull acc[4][4];
#pragma unroll
    for (int i = 0; i < 4; i++)
#pragma unroll
        for (int j = 0; j < 4; j++) acc[i][j] = 0ULL;

    const int stok = tid >> 2, sj4 = tid & 3;          // xs staging
    const int skk = tid >> 3, scb = (tid & 7) * 16;    // ws staging

    for (int kt = 0; kt < 4; kt++) {
        // ---- stage X splatted ----
        const float* xp = X + stok * 2048 + k0 + kt * 32 + sj4 * 8;
        float4 a = *(const float4*)xp;
        float4 b4 = *(const float4*)(xp + 4);
        float* xd = xs + stok * 68 + sj4 * 16;
        *(float4*)(xd + 0)  = make_float4(a.x, a.x, a.y, a.y);
        *(float4*)(xd + 4)  = make_float4(a.z, a.z, a.w, a.w);
        *(float4*)(xd + 8)  = make_float4(b4.x, b4.x, b4.y, b4.y);
        *(float4*)(xd + 12) = make_float4(b4.z, b4.z, b4.w, b4.w);
        // ---- stage W ----
        const float* wp = W + (size_t)(k0 + kt * 32 + skk) * Wn + Wc + scb;
        float* wd = ws + skk * 132 + scb;
#pragma unroll
        for (int i = 0; i < 4; i++)
            *(float4*)(wd + 4 * i) = *(const float4*)(wp + 4 * i);
        __syncthreads();

#pragma unroll 4
        for (int kkp = 0; kkp < 16; kkp++) {
            ulonglong2 xv[4];
#pragma unroll
            for (int i = 0; i < 4; i++)
                xv[i] = *(const ulonglong2*)(xs + (4 * ty + i) * 68 + 4 * kkp);
            ulonglong2 w0a = *(const ulonglong2*)(ws + (2 * kkp) * 132 + 4 * tx);
            ulonglong2 w0b = *(const ulonglong2*)(ws + (2 * kkp) * 132 + 64 + 4 * tx);
            ulonglong2 w1a = *(const ulonglong2*)(ws + (2 * kkp + 1) * 132 + 4 * tx);
            ulonglong2 w1b = *(const ulonglong2*)(ws + (2 * kkp + 1) * 132 + 64 + 4 * tx);
#pragma unroll
            for (int i = 0; i < 4; i++) {
                fma2(acc[i][0], xv[i].x, w0a.x);
                fma2(acc[i][1], xv[i].x, w0a.y);
                fma2(acc[i][2], xv[i].x, w0b.x);
                fma2(acc[i][3], xv[i].x, w0b.y);
                fma2(acc[i][0], xv[i].y, w1a.x);
                fma2(acc[i][1], xv[i].y, w1a.y);
                fma2(acc[i][2], xv[i].y, w1b.x);
                fma2(acc[i][3], xv[i].y, w1b.y);
            }
        }
        __syncthreads();
    }
#pragma unroll
    for (int i = 0; i < 4; i++) {
        float2 a0 = unpack2(acc[i][0]), a1 = unpack2(acc[i][1]);
        float2 a2 = unpack2(acc[i][2]), a3 = unpack2(acc[i][3]);
        float* dst = P + ((size_t)ks * 64 + 4 * ty + i) * Pn + ob + 4 * tx;
        *(float4*)dst        = make_float4(a0.x, a0.y, a1.x, a1.y);
        *(float4*)(dst + 64) = make_float4(a2.x, a2.y, a3.x, a3.y);
    }
}

// ---------------------------------------------------------------------------
// Reduce QKV k-split partials + fused RoPE
// ---------------------------------------------------------------------------
__global__ void reduce_rope_kernel() {
    int gid = blockIdx.x * 256 + threadIdx.x;
    if (gid >= 64 * 1536) return;
    int token = gid / 1536;
    int r = gid - token * 1536;
    int t = token & 3;
    const float* P = &g_qkv_part[0][0][0];

    int h, i, c1;
    bool is_q = (r < 1024), is_k = (!is_q && r < 1280);
    if (is_q)      { h = r >> 6;              i = r & 63; c1 = h * 128 + i; }
    else if (is_k) { int rr = r - 1024; h = rr >> 6; i = rr & 63; c1 = 2048 + h * 128 + i; }
    else           { int rr = r - 1280; h = rr >> 6; i = rr & 63; c1 = 2560 + h * 128 + i; }

    float s1 = 0.f, s2 = 0.f;
#pragma unroll
    for (int ks = 0; ks < KSPLIT; ks++) {
        const float* row = P + ((size_t)ks * 64 + token) * 3072;
        s1 += row[c1];
        s2 += row[c1 + 64];
    }
    if (!is_q && !is_k) {
        g_v[token * 512 + h * 128 + i] = s1;
        g_v[token * 512 + h * 128 + i + 64] = s2;
        return;
    }
    float cs = g_cos[t][i], sn = g_sin[t][i];
    float o1 = s1 * cs - s2 * sn;
    float o2 = s1 * sn + s2 * cs;
    if (is_q) {
        g_q[token * 2048 + c1] = o1;
        g_q[token * 2048 + c1 + 64] = o2;
    } else {
        int cc = h * 128 + i;
        g_k[token * 512 + cc] = o1;
        g_k[token * 512 + cc + 64] = o2;
    }
}

// ---------------------------------------------------------------------------
// Attention: CTA = (pair, split). Pass1: d-chunked (8 d at a time) over ALL
// 256 keys, f32x2 packed over d, 4q x 4k register tile. Pass2: 2q x 4d.
// smem: q[16][134] + at[16][262] + m/l + kv buffer (max 8448)
// ---------------------------------------------------------------------------
#define ATS 262
#define ATTN_SMEM_FLOATS (2144 + 4192 + 32 + 8448)
#define ATTN_SMEM_BYTES (ATTN_SMEM_FLOATS * 4)

__global__ void attn_kernel(const float* __restrict__ ck,
                            const float* __restrict__ cv) {
    extern __shared__ float sm[];
    float* q_s  = sm;                 // [16][134]
    float* at_s = sm + 2144;          // [16][262]
    float* m_s  = at_s + 4192;        // [16]
    float* l_s  = m_s + 16;           // [16]
    float* kv_s = l_s + 16;           // pass1: [128 keypairs][18] ; pass2: [64][132]

    const int tid = threadIdx.x;
    const int split = blockIdx.x % NSPLITS;
    const int pair  = blockIdx.x / NSPLITS;
    const int b = pair >> 2, kvh = pair & 3;
    const int len = (split < 8) ? 256 : 4;
    const float scale = 0.08838834764831845f;

    // ---- stage Q [16][134] ----
#pragma unroll
    for (int i = 0; i < 8; i++) {
        int idx = tid + i * 256;
        int row = idx >> 7, d = idx & 127;
        int hg = row >> 2, t = row & 3;
        q_s[row * 134 + d] = g_q[(b * 4 + t) * 2048 + (kvh * 4 + hg) * 128 + d];
    }

    // key source row for this thread's staging (key = tid)
    const float* ksrc;
    {
        int key = tid;
        if (split < 8) {
            int se = split * 256 + key;
            int crow = (se < 4) ? se : se + 2048;
            ksrc = ck + ((size_t)(b * 4 + kvh) * 4096 + crow) * 128;
        } else {
            int t = (key < 4) ? key : 0;
            ksrc = g_k + (b * 4 + t) * 512 + kvh * 128;
        }
    }

    const int qg = tid & 3;        // q rows 4qg..4qg+3
    const int kb = tid >> 2;       // keys 4kb..4kb+3
    ull acc[4][4];
#pragma unroll
    for (int i = 0; i < 4; i++)
#pragma unroll
        for (int j = 0; j < 4; j++) acc[i][j] = 0ULL;

    const int kvbase = (2 * kb) * 18;   // key-pair row base for reads

    // ---- Pass 1: 16 chunks of 8 d ----
    for (int dc = 0; dc < 16; dc++) {
        __syncthreads();
        {   // stage [256 keys][8 d] as key-pair interleaved [128][18]
            float4 u = *(const float4*)(ksrc + dc * 8);
            float4 w = *(const float4*)(ksrc + dc * 8 + 4);
            float* dst = kv_s + (tid >> 1) * 18 + (tid & 1) * 2;
            *(float2*)(dst + 0)  = make_float2(u.x, u.y);
            *(float2*)(dst + 4)  = make_float2(u.z, u.w);
            *(float2*)(dst + 8)  = make_float2(w.x, w.y);
            *(float2*)(dst + 12) = make_float2(w.z, w.w);
        }
        __syncthreads();

        const float* qb = q_s + (4 * qg) * 134 + dc * 8;
        // rows 0,1
        {
            ull q0[4], q1[4];
#pragma unroll
            for (int dp = 0; dp < 4; dp++) {
                q0[dp] = *(const ull*)(qb + 2 * dp);
                q1[dp] = *(const ull*)(qb + 134 + 2 * dp);
            }
#pragma unroll
            for (int jh = 0; jh < 2; jh++)
#pragma unroll
                for (int jl = 0; jl < 2; jl++) {
                    const float* kr = kv_s + kvbase + jh * 18 + 2 * jl;
#pragma unroll
                    for (int dp = 0; dp < 4; dp++) {
                        ull kv = *(const ull*)(kr + 4 * dp);
                        fma2(acc[0][jh * 2 + jl], q0[dp], kv);
                        fma2(acc[1][jh * 2 + jl], q1[dp], kv);
                    }
                }
        }
        // rows 2,3
        {
            ull q2[4], q3[4];
#pragma unroll
            for (int dp = 0; dp < 4; dp++) {
                q2[dp] = *(const ull*)(qb + 2 * 134 + 2 * dp);
                q3[dp] = *(const ull*)(qb + 3 * 134 + 2 * dp);
            }
#pragma unroll
            for (int jh = 0; jh < 2; jh++)
#pragma unroll
                for (int jl = 0; jl < 2; jl++) {
                    const float* kr = kv_s + kvbase + jh * 18 + 2 * jl;
#pragma unroll
                    for (int dp = 0; dp < 4; dp++) {
                        ull kv = *(const ull*)(kr + 4 * dp);
                        fma2(acc[2][jh * 2 + jl], q2[dp], kv);
                        fma2(acc[3][jh * 2 + jl], q3[dp], kv);
                    }
                }
        }
    }
    // write scores
#pragma unroll
    for (int r = 0; r < 4; r++)
#pragma unroll
        for (int j = 0; j < 4; j++) {
            float2 f = unpack2(acc[r][j]);
            at_s[(4 * qg + r) * ATS + 4 * kb + j] = (f.x + f.y) * scale;
        }
    __syncthreads();

    // ---- softmax: warp w owns rows 2w, 2w+1 ----
    {
        int w = tid >> 5, lane = tid & 31;
#pragma unroll
        for (int rr = 0; rr < 2; rr++) {
            int r = w * 2 + rr;
            float* row = at_s + r * ATS;
            float m = -3.0e38f;
            for (int s = lane; s < len; s += 32) m = fmaxf(m, row[s]);
#pragma unroll
            for (int off = 16; off; off >>= 1)
                m = fmaxf(m, __shfl_xor_sync(0xffffffffu, m, off));
            float l = 0.f;
            for (int s = lane; s < len; s += 32) {
                float e = __expf(row[s] - m);
                row[s] = e;
                l += e;
            }
#pragma unroll
            for (int off = 16; off; off >>= 1)
                l += __shfl_xor_sync(0xffffffffu, l, off);
            if (lane == 0) { m_s[r] = m; l_s[r] = l; }
        }
    }

    // ---- Pass 2: O = P @ V, thread = 2 q rows x 4 d cols ----
    const int qp = tid & 7;    // rows 2qp, 2qp+1
    const int db = tid >> 3;   // cols 4db..4db+3
    ull o00 = 0ULL, o01 = 0ULL, o10 = 0ULL, o11 = 0ULL;
    const int NT = (split < 8) ? 4 : 1;
    const int vrow = tid >> 2, vcb = (tid & 3) * 32;

    for (int tile = 0; tile < NT; tile++) {
        __syncthreads();
        {   // stage V tile [64][132]
            int sl = tile * 64 + vrow;
            const float* src;
            if (split < 8) {
                int se = split * 256 + sl;
                int crow = (se < 4) ? se : se + 2048;
                src = cv + ((size_t)(b * 4 + kvh) * 4096 + crow) * 128;
            } else {
                int t = (sl < 4) ? sl : 0;
                src = g_v + (b * 4 + t) * 512 + kvh * 128;
            }
            float* dst = kv_s + vrow * 132 + vcb;
#pragma unroll
            for (int i = 0; i < 8; i++)
                *(float4*)(dst + 4 * i) = *(const float4*)(src + vcb + 4 * i);
        }
        __syncthreads();

        int sbound = len - tile * 64;
        if (sbound > 64) sbound = 64;
        const float* p0r = at_s + (2 * qp) * ATS + tile * 64;
        const float* p1r = p0r + ATS;
        for (int s0 = 0; s0 < sbound; s0 += 2) {
            float2 p0 = *(const float2*)(p0r + s0);
            float2 p1 = *(const float2*)(p1r + s0);
            const float* v0 = kv_s + s0 * 132 + 4 * db;
            ull va = *(const ull*)v0;
            ull vb = *(const ull*)(v0 + 2);
            ull pa0 = pack2(p0.x, p0.x), pa1 = pack2(p1.x, p1.x);
            fma2(o00, pa0, va); fma2(o01, pa0, vb);
            fma2(o10, pa1, va); fma2(o11, pa1, vb);
            const float* v1 = v0 + 132;
            ull vc = *(const ull*)v1;
            ull vd = *(const ull*)(v1 + 2);
            ull pb0 = pack2(p0.y, p0.y), pb1 = pack2(p1.y, p1.y);
            fma2(o00, pb0, vc); fma2(o01, pb0, vd);
            fma2(o10, pb1, vc); fma2(o11, pb1, vd);
        }
    }

    // write partials + stats
    {
        size_t base = (size_t)(pair * NSPLITS + split) * 16;
        float2 a = unpack2(o00), c = unpack2(o01);
        *(float4*)(g_po + (base + 2 * qp) * 128 + 4 * db) =
            make_float4(a.x, a.y, c.x, c.y);
        float2 e = unpack2(o10), f = unpack2(o11);
        *(float4*)(g_po + (base + 2 * qp + 1) * 128 + 4 * db) =
            make_float4(e.x, e.y, f.x, f.y);
        __syncthreads();
        if (tid < 16) {
            g_pm[base + tid] = m_s[tid];
            g_pl[base + tid] = l_s[tid];
        }
    }
}

// ---------------------------------------------------------------------------
// Combine split partials -> g_y
// ---------------------------------------------------------------------------
__global__ void combine_kernel() {
    int bidx = blockIdx.x;
    int pair = bidx >> 4, q = bidx & 15;
    int d = threadIdx.x;
    int hg = q >> 2, t = q & 3;
    int b = pair >> 2, kvh = pair & 3;

    float ms[NSPLITS];
    float M = -3.0e38f;
#pragma unroll
    for (int i = 0; i < NSPLITS; i++) {
        ms[i] = g_pm[(pair * NSPLITS + i) * 16 + q];
        M = fmaxf(M, ms[i]);
    }
    float L = 0.f, acc = 0.f;
#pragma unroll
    for (int i = 0; i < NSPLITS; i++) {
        float w = __expf(ms[i] - M);
        L += w * g_pl[(pair * NSPLITS + i) * 16 + q];
        acc += w * g_po[((size_t)(pair * NSPLITS + i) * 16 + q) * 128 + d];
    }
    g_y[(b * 4 + t) * 2048 + (kvh * 4 + hg) * 128 + d] = acc / L;
}

// ---------------------------------------------------------------------------
// Sum k-split out-proj partials -> d_out (vectorized)
// ---------------------------------------------------------------------------
__global__ void reduce_out_kernel(float* __restrict__ out) {
    int gid = blockIdx.x * 256 + threadIdx.x;
    if (gid >= 64 * 2048 / 4) return;
    const float4* P = (const float4*)&g_out_part[0][0][0];
    float4 s = make_float4(0.f, 0.f, 0.f, 0.f);
#pragma unroll
    for (int ks = 0; ks < KSPLIT; ks++) {
        float4 v = P[(size_t)ks * 32768 + gid];
        s.x += v.x; s.y += v.y; s.z += v.z; s.w += v.w;
    }
    ((float4*)out)[gid] = s;
}

// ---------------------------------------------------------------------------
extern "C" void kernel_launch(void* const* d_in, const int* in_sizes, int n_in,
                              void* d_out, int out_size) {
    const float* x     = (const float*)d_in[0];
    const float* ck    = (const float*)d_in[1];
    const float* cv    = (const float*)d_in[2];
    const float* wq    = (const float*)d_in[3];
    const float* wk    = (const float*)d_in[4];
    const float* wv    = (const float*)d_in[5];
    const float* wproj = (const float*)d_in[6];
    const int*   sp    = (const int*)d_in[7];
    float* out = (float*)d_out;

    float *qkvp, *yp, *outp;
    cudaGetSymbolAddress((void**)&qkvp, g_qkv_part);
    cudaGetSymbolAddress((void**)&yp, g_y);
    cudaGetSymbolAddress((void**)&outp, g_out_part);

    cudaFuncSetAttribute(attn_kernel,
                         cudaFuncAttributeMaxDynamicSharedMemorySize,
                         ATTN_SMEM_BYTES);

    rope_table_kernel<<<8, 32>>>(sp);
    gemm_big<<<dim3(24, KSPLIT), 256>>>(x, wq, wk, wv, qkvp, 3072, 1);
    reduce_rope_kernel<<<384, 256>>>();
    attn_kernel<<<64 * NSPLITS, 256, ATTN_SMEM_BYTES>>>(ck, cv);
    combine_kernel<<<1024, 128>>>();
    gemm_big<<<dim3(16, KSPLIT), 256>>>(yp, wproj, wproj, wproj, outp, 2048, 0);
    reduce_out_kernel<<<128, 256>>>(out);
}

// round 4
// speedup vs baseline: 1.5630x; 1.2979x over previous
#include <cuda_runtime.h>
#include <math.h>

// B=16, T=4, C=2048, 16 heads / 4 kv heads, d=128, S_cache=4096,
// window=2048, sink=4 -> 2052 effective keys.
// Key s: s<4 -> cache row s ; 4<=s<2048 -> cache row s+2048 ; s>=2048 -> new.

#define KSPLIT 16
#define NSPLITS 9   // 8 x 256 cached keys + 1 x 4 new keys

__device__ float g_qkv_part[KSPLIT][64][3072];
__device__ float g_q[64 * 2048];
__device__ float g_k[64 * 512];
__device__ float g_v[64 * 512];
__device__ float g_po[64 * NSPLITS * 16 * 128];
__device__ float g_pm[64 * NSPLITS * 16];
__device__ float g_pl[64 * NSPLITS * 16];
__device__ float g_y[64 * 2048];
__device__ float g_out_part[KSPLIT][64][2048];
__device__ float g_cos[4][64];
__device__ float g_sin[4][64];

typedef unsigned long long ull;

__device__ __forceinline__ void fma2(ull& d, ull a, ull b) {
    asm("fma.rn.f32x2 %0, %1, %2, %0;" : "+l"(d) : "l"(a), "l"(b));
}
__device__ __forceinline__ ull pack2(float x, float y) {
    ull r;
    asm("mov.b64 %0, {%1, %2};" : "=l"(r) : "f"(x), "f"(y));
    return r;
}
__device__ __forceinline__ float2 unpack2(ull v) {
    float2 r;
    asm("mov.b64 {%0, %1}, %2;" : "=f"(r.x), "=f"(r.y) : "l"(v));
    return r;
}

// ---------------------------------------------------------------------------
__global__ void rope_table_kernel(const int* __restrict__ sp) {
    int tid = blockIdx.x * 32 + threadIdx.x;
    if (tid >= 256) return;
    int t = tid >> 6, i = tid & 63;
    double f = exp2(-(double)i * (13.287712379549449 / 64.0));
    double ang = (double)(sp[0] + t) * f;
    double s, c;
    sincos(ang, &s, &c);
    g_cos[t][i] = (float)c;
    g_sin[t][i] = (float)s;
}

// ---------------------------------------------------------------------------
// Big GEMM: 64 tokens x 128-col tile, K-chunk 128 (ksplit 16).
// qkv=1: fused QKV (ctile 0-15 wq, 16-19 wk, 20-23 wv). qkv=0: wa only.
// ---------------------------------------------------------------------------
__global__ void gemm_big(const float* __restrict__ X,
                         const float* __restrict__ wa,
                         const float* __restrict__ wb,
                         const float* __restrict__ wc,
                         float* __restrict__ P, int Pn, int qkv) {
    const int tid = threadIdx.x;
    const int ct = blockIdx.x, ks = blockIdx.y;
    const float* W;
    int Wn, Wc, ob;
    if (qkv) {
        if (ct < 16)      { W = wa; Wn = 2048; Wc = ct * 128;        ob = Wc; }
        else if (ct < 20) { W = wb; Wn = 512;  Wc = (ct - 16) * 128; ob = 2048 + Wc; }
        else              { W = wc; Wn = 512;  Wc = (ct - 20) * 128; ob = 2560 + Wc; }
    } else { W = wa; Wn = 2048; Wc = ct * 128; ob = Wc; }
    const int k0 = ks * 128;

    __shared__ float xs[64 * 68];
    __shared__ float ws[32 * 132];

    const int tx = tid & 15, ty = tid >> 4;
    ull acc[4][4];
#pragma unroll
    for (int i = 0; i < 4; i++)
#pragma unroll
        for (int j = 0; j < 4; j++) acc[i][j] = 0ULL;

    const int stok = tid >> 2, sj4 = tid & 3;
    const int skk = tid >> 3, scb = (tid & 7) * 16;

    for (int kt = 0; kt < 4; kt++) {
        const float* xp = X + stok * 2048 + k0 + kt * 32 + sj4 * 8;
        float4 a = *(const float4*)xp;
        float4 b4 = *(const float4*)(xp + 4);
        float* xd = xs + stok * 68 + sj4 * 16;
        *(float4*)(xd + 0)  = make_float4(a.x, a.x, a.y, a.y);
        *(float4*)(xd + 4)  = make_float4(a.z, a.z, a.w, a.w);
        *(float4*)(xd + 8)  = make_float4(b4.x, b4.x, b4.y, b4.y);
        *(float4*)(xd + 12) = make_float4(b4.z, b4.z, b4.w, b4.w);
        const float* wp = W + (size_t)(k0 + kt * 32 + skk) * Wn + Wc + scb;
        float* wd = ws + skk * 132 + scb;
#pragma unroll
        for (int i = 0; i < 4; i++)
            *(float4*)(wd + 4 * i) = *(const float4*)(wp + 4 * i);
        __syncthreads();

#pragma unroll 4
        for (int kkp = 0; kkp < 16; kkp++) {
            ulonglong2 xv[4];
#pragma unroll
            for (int i = 0; i < 4; i++)
                xv[i] = *(const ulonglong2*)(xs + (4 * ty + i) * 68 + 4 * kkp);
            ulonglong2 w0a = *(const ulonglong2*)(ws + (2 * kkp) * 132 + 4 * tx);
            ulonglong2 w0b = *(const ulonglong2*)(ws + (2 * kkp) * 132 + 64 + 4 * tx);
            ulonglong2 w1a = *(const ulonglong2*)(ws + (2 * kkp + 1) * 132 + 4 * tx);
            ulonglong2 w1b = *(const ulonglong2*)(ws + (2 * kkp + 1) * 132 + 64 + 4 * tx);
#pragma unroll
            for (int i = 0; i < 4; i++) {
                fma2(acc[i][0], xv[i].x, w0a.x);
                fma2(acc[i][1], xv[i].x, w0a.y);
                fma2(acc[i][2], xv[i].x, w0b.x);
                fma2(acc[i][3], xv[i].x, w0b.y);
                fma2(acc[i][0], xv[i].y, w1a.x);
                fma2(acc[i][1], xv[i].y, w1a.y);
                fma2(acc[i][2], xv[i].y, w1b.x);
                fma2(acc[i][3], xv[i].y, w1b.y);
            }
        }
        __syncthreads();
    }
#pragma unroll
    for (int i = 0; i < 4; i++) {
        float2 a0 = unpack2(acc[i][0]), a1 = unpack2(acc[i][1]);
        float2 a2 = unpack2(acc[i][2]), a3 = unpack2(acc[i][3]);
        float* dst = P + ((size_t)ks * 64 + 4 * ty + i) * Pn + ob + 4 * tx;
        *(float4*)dst        = make_float4(a0.x, a0.y, a1.x, a1.y);
        *(float4*)(dst + 64) = make_float4(a2.x, a2.y, a3.x, a3.y);
    }
}

// ---------------------------------------------------------------------------
__global__ void reduce_rope_kernel() {
    int gid = blockIdx.x * 256 + threadIdx.x;
    if (gid >= 64 * 1536) return;
    int token = gid / 1536;
    int r = gid - token * 1536;
    int t = token & 3;
    const float* P = &g_qkv_part[0][0][0];

    int h, i, c1;
    bool is_q = (r < 1024), is_k = (!is_q && r < 1280);
    if (is_q)      { h = r >> 6;              i = r & 63; c1 = h * 128 + i; }
    else if (is_k) { int rr = r - 1024; h = rr >> 6; i = rr & 63; c1 = 2048 + h * 128 + i; }
    else           { int rr = r - 1280; h = rr >> 6; i = rr & 63; c1 = 2560 + h * 128 + i; }

    float s1 = 0.f, s2 = 0.f;
#pragma unroll
    for (int ks = 0; ks < KSPLIT; ks++) {
        const float* row = P + ((size_t)ks * 64 + token) * 3072;
        s1 += row[c1];
        s2 += row[c1 + 64];
    }
    if (!is_q && !is_k) {
        g_v[token * 512 + h * 128 + i] = s1;
        g_v[token * 512 + h * 128 + i + 64] = s2;
        return;
    }
    float cs = g_cos[t][i], sn = g_sin[t][i];
    float o1 = s1 * cs - s2 * sn;
    float o2 = s1 * sn + s2 * cs;
    if (is_q) {
        g_q[token * 2048 + c1] = o1;
        g_q[token * 2048 + c1 + 64] = o2;
    } else {
        int cc = h * 128 + i;
        g_k[token * 512 + cc] = o1;
        g_k[token * 512 + cc + 64] = o2;
    }
}

// ---------------------------------------------------------------------------
// Attention. CTA = (pair, split). All staging coalesced (warp = key rows).
// Pass1: 4 stages of 32 d; smem K layout [keypair][66] (keys interleaved as
// f32x2 over d) -> conflict-free LDS.64; thread tile 4q x 4k, single K load.
// Pass2: 4 tiles of 64 V rows [64][132]; thread tile 2q x 4d.
// smem total = 2080 + 4192 + 32 + 8448 = 14752 floats (59 KB), 3 CTAs/SM.
// ---------------------------------------------------------------------------
#define ATS 262
#define ATTN_SMEM_BYTES (14752 * 4)

__global__ void __launch_bounds__(256, 3)
attn_kernel(const float* __restrict__ ck, const float* __restrict__ cv) {
    extern __shared__ float sm[];
    float* q_s  = sm;                 // [16][130]
    float* at_s = sm + 2080;          // [16][262]
    float* m_s  = at_s + 4192;        // [16]
    float* l_s  = m_s + 16;           // [16]
    float* kv_s = l_s + 16;           // pass1 [128 kp][66] / pass2 [64][132]

    const int tid = threadIdx.x;
    const int split = blockIdx.x % NSPLITS;
    const int pair  = blockIdx.x / NSPLITS;
    const int b = pair >> 2, kvh = pair & 3;
    const int len = (split < 8) ? 256 : 4;
    const float scale = 0.08838834764831845f;

    const float* cache_base_k = ck + (size_t)(b * 4 + kvh) * 4096 * 128;
    const float* cache_base_v = cv + (size_t)(b * 4 + kvh) * 4096 * 128;
    const float* gk_base = g_k + (b * 4) * 512 + kvh * 128;
    const float* gv_base = g_v + (b * 4) * 512 + kvh * 128;

    // ---- stage Q [16][130] ----
#pragma unroll
    for (int i = 0; i < 8; i++) {
        int idx = tid + i * 256;
        int row = idx >> 7, d = idx & 127;
        int hg = row >> 2, t = row & 3;
        q_s[row * 130 + d] = g_q[(b * 4 + t) * 2048 + (kvh * 4 + hg) * 128 + d];
    }

    const int w   = tid >> 5, lane = tid & 31;
    const int lk  = lane >> 3;          // key sub 0..3
    const int ld4 = (lane & 7) * 4;     // d offset within stage
    const int qg = tid & 3;             // q rows 4qg..4qg+3
    const int kb = tid >> 2;            // keys 4kb..4kb+3

    ull acc[4][4];
#pragma unroll
    for (int i = 0; i < 4; i++)
#pragma unroll
        for (int j = 0; j < 4; j++) acc[i][j] = 0ULL;

    // ---- Pass 1: 4 stages of 32 d over all 256 keys ----
#pragma unroll 1
    for (int s = 0; s < 4; s++) {
        __syncthreads();
        // coalesced staging: warp covers keys w*32..w*32+31, 128B/key/stage
#pragma unroll
        for (int r = 0; r < 8; r++) {
            int key = w * 32 + r * 4 + lk;
            const float* src;
            if (split < 8) {
                int se = split * 256 + key;
                int crow = (se < 4) ? se : se + 2048;
                src = cache_base_k + (size_t)crow * 128;
            } else {
                int t = (key < 4) ? key : 0;
                src = gk_base + t * 512;
            }
            float4 v = *(const float4*)(src + s * 32 + ld4);
            float* dst = kv_s + (key >> 1) * 66 + (lane & 7) * 8 + (key & 1) * 2;
            *(float2*)dst       = make_float2(v.x, v.y);
            *(float2*)(dst + 4) = make_float2(v.z, v.w);
        }
        __syncthreads();

#pragma unroll
        for (int dcl = 0; dcl < 4; dcl++) {     // 8 d per dcl
            const float* qb = q_s + s * 32 + dcl * 8;
            const float* kbse = kv_s + (2 * kb) * 66 + dcl * 16;
#pragma unroll
            for (int dp = 0; dp < 4; dp++) {
                ull q0 = *(const ull*)(qb + (4 * qg + 0) * 130 + 2 * dp);
                ull q1 = *(const ull*)(qb + (4 * qg + 1) * 130 + 2 * dp);
                ull q2 = *(const ull*)(qb + (4 * qg + 2) * 130 + 2 * dp);
                ull q3 = *(const ull*)(qb + (4 * qg + 3) * 130 + 2 * dp);
#pragma unroll
                for (int jh = 0; jh < 2; jh++)
#pragma unroll
                    for (int jl = 0; jl < 2; jl++) {
                        ull kv = *(const ull*)(kbse + jh * 66 + dp * 4 + jl * 2);
                        fma2(acc[0][jh * 2 + jl], q0, kv);
                        fma2(acc[1][jh * 2 + jl], q1, kv);
                        fma2(acc[2][jh * 2 + jl], q2, kv);
                        fma2(acc[3][jh * 2 + jl], q3, kv);
                    }
            }
        }
    }
    // write scores
#pragma unroll
    for (int r = 0; r < 4; r++)
#pragma unroll
        for (int j = 0; j < 4; j++) {
            float2 f = unpack2(acc[r][j]);
            at_s[(4 * qg + r) * ATS + 4 * kb + j] = (f.x + f.y) * scale;
        }
    __syncthreads();

    // ---- softmax: warp w owns rows 2w, 2w+1 ----
    {
#pragma unroll
        for (int rr = 0; rr < 2; rr++) {
            int r = w * 2 + rr;
            float* row = at_s + r * ATS;
            float m = -3.0e38f;
            for (int sx = lane; sx < len; sx += 32) m = fmaxf(m, row[sx]);
#pragma unroll
            for (int off = 16; off; off >>= 1)
                m = fmaxf(m, __shfl_xor_sync(0xffffffffu, m, off));
            float l = 0.f;
            for (int sx = lane; sx < len; sx += 32) {
                float e = __expf(row[sx] - m);
                row[sx] = e;
                l += e;
            }
#pragma unroll
            for (int off = 16; off; off >>= 1)
                l += __shfl_xor_sync(0xffffffffu, l, off);
            if (lane == 0) { m_s[r] = m; l_s[r] = l; }
        }
    }

    // ---- Pass 2: O = P @ V ; thread = 2 q rows x 4 d cols ----
    const int qp = tid & 7;
    const int db = tid >> 3;
    ull o00 = 0ULL, o01 = 0ULL, o10 = 0ULL, o11 = 0ULL;
    const int NT = (split < 8) ? 4 : 1;

#pragma unroll 1
    for (int tile = 0; tile < NT; tile++) {
        __syncthreads();
        // coalesced staging: warp = one V row per round
#pragma unroll
        for (int r = 0; r < 8; r++) {
            int lrow = w * 8 + r;
            int sl = tile * 64 + lrow;
            const float* src;
            if (split < 8) {
                int se = split * 256 + sl;
                int crow = (se < 4) ? se : se + 2048;
                src = cache_base_v + (size_t)crow * 128;
            } else {
                int t = (sl < 4) ? sl : 0;
                src = gv_base + t * 512;
            }
            *(float4*)(kv_s + lrow * 132 + lane * 4) =
                *(const float4*)(src + lane * 4);
        }
        __syncthreads();

        int sbound = len - tile * 64;
        if (sbound > 64) sbound = 64;
        const float* p0r = at_s + (2 * qp) * ATS + tile * 64;
        const float* p1r = p0r + ATS;
        for (int s0 = 0; s0 < sbound; s0 += 2) {
            float2 p0 = *(const float2*)(p0r + s0);
            float2 p1 = *(const float2*)(p1r + s0);
            const float* v0 = kv_s + s0 * 132 + 4 * db;
            ull va = *(const ull*)v0;
            ull vb = *(const ull*)(v0 + 2);
            ull pa0 = pack2(p0.x, p0.x), pa1 = pack2(p1.x, p1.x);
            fma2(o00, pa0, va); fma2(o01, pa0, vb);
            fma2(o10, pa1, va); fma2(o11, pa1, vb);
            const float* v1 = v0 + 132;
            ull vc = *(const ull*)v1;
            ull vd = *(const ull*)(v1 + 2);
            ull pb0 = pack2(p0.y, p0.y), pb1 = pack2(p1.y, p1.y);
            fma2(o00, pb0, vc); fma2(o01, pb0, vd);
            fma2(o10, pb1, vc); fma2(o11, pb1, vd);
        }
    }

    // write partials + stats
    {
        size_t base = (size_t)(pair * NSPLITS + split) * 16;
        float2 a = unpack2(o00), c = unpack2(o01);
        *(float4*)(g_po + (base + 2 * qp) * 128 + 4 * db) =
            make_float4(a.x, a.y, c.x, c.y);
        float2 e = unpack2(o10), f = unpack2(o11);
        *(float4*)(g_po + (base + 2 * qp + 1) * 128 + 4 * db) =
            make_float4(e.x, e.y, f.x, f.y);
        __syncthreads();
        if (tid < 16) {
            g_pm[base + tid] = m_s[tid];
            g_pl[base + tid] = l_s[tid];
        }
    }
}

// ---------------------------------------------------------------------------
__global__ void combine_kernel() {
    int bidx = blockIdx.x;
    int pair = bidx >> 4, q = bidx & 15;
    int d = threadIdx.x;
    int hg = q >> 2, t = q & 3;
    int b = pair >> 2, kvh = pair & 3;

    float ms[NSPLITS];
    float M = -3.0e38f;
#pragma unroll
    for (int i = 0; i < NSPLITS; i++) {
        ms[i] = g_pm[(pair * NSPLITS + i) * 16 + q];
        M = fmaxf(M, ms[i]);
    }
    float L = 0.f, acc = 0.f;
#pragma unroll
    for (int i = 0; i < NSPLITS; i++) {
        float wgt = __expf(ms[i] - M);
        L += wgt * g_pl[(pair * NSPLITS + i) * 16 + q];
        acc += wgt * g_po[((size_t)(pair * NSPLITS + i) * 16 + q) * 128 + d];
    }
    g_y[(b * 4 + t) * 2048 + (kvh * 4 + hg) * 128 + d] = acc / L;
}

// ---------------------------------------------------------------------------
__global__ void reduce_out_kernel(float* __restrict__ out) {
    int gid = blockIdx.x * 256 + threadIdx.x;
    if (gid >= 64 * 2048 / 4) return;
    const float4* P = (const float4*)&g_out_part[0][0][0];
    float4 s = make_float4(0.f, 0.f, 0.f, 0.f);
#pragma unroll
    for (int ks = 0; ks < KSPLIT; ks++) {
        float4 v = P[(size_t)ks * 32768 + gid];
        s.x += v.x; s.y += v.y; s.z += v.z; s.w += v.w;
    }
    ((float4*)out)[gid] = s;
}

// ---------------------------------------------------------------------------
extern "C" void kernel_launch(void* const* d_in, const int* in_sizes, int n_in,
                              void* d_out, int out_size) {
    const float* x     = (const float*)d_in[0];
    const float* ck    = (const float*)d_in[1];
    const float* cv    = (const float*)d_in[2];
    const float* wq    = (const float*)d_in[3];
    const float* wk    = (const float*)d_in[4];
    const float* wv    = (const float*)d_in[5];
    const float* wproj = (const float*)d_in[6];
    const int*   sp    = (const int*)d_in[7];
    float* out = (float*)d_out;

    float *qkvp, *yp, *outp;
    cudaGetSymbolAddress((void**)&qkvp, g_qkv_part);
    cudaGetSymbolAddress((void**)&yp, g_y);
    cudaGetSymbolAddress((void**)&outp, g_out_part);

    cudaFuncSetAttribute(attn_kernel,
                         cudaFuncAttributeMaxDynamicSharedMemorySize,
                         ATTN_SMEM_BYTES);

    rope_table_kernel<<<8, 32>>>(sp);
    gemm_big<<<dim3(24, KSPLIT), 256>>>(x, wq, wk, wv, qkvp, 3072, 1);
    reduce_rope_kernel<<<384, 256>>>();
    attn_kernel<<<64 * NSPLITS, 256, ATTN_SMEM_BYTES>>>(ck, cv);
    combine_kernel<<<1024, 128>>>();
    gemm_big<<<dim3(16, KSPLIT), 256>>>(yp, wproj, wproj, wproj, outp, 2048, 0);
    reduce_out_kernel<<<128, 256>>>(out);
}

// round 5
// speedup vs baseline: 1.7758x; 1.1362x over previous
#include <cuda_runtime.h>
#include <math.h>

// B=16, T=4, C=2048, 16 heads / 4 kv heads, d=128, S_cache=4096,
// window=2048, sink=4 -> 2052 effective keys.
// Key s: s<4 -> cache row s ; 4<=s<2048 -> cache row s+2048 ; s>=2048 -> new.

#define KSPLIT 16
#define NSPLITS 9   // 8 x 256 cached keys + 1 x 4 new keys

__device__ float g_qkv_part[KSPLIT][64][3072];
__device__ float g_q[64 * 2048];
__device__ float g_k[64 * 512];
__device__ float g_v[64 * 512];
__device__ float g_po[64 * NSPLITS * 16 * 128];
__device__ float g_pm[64 * NSPLITS * 16];
__device__ float g_pl[64 * NSPLITS * 16];
__device__ float g_y[64 * 2048];
__device__ float g_out_part[KSPLIT][64][2048];
__device__ float g_cos[4][64];
__device__ float g_sin[4][64];

typedef unsigned long long ull;

__device__ __forceinline__ void fma2(ull& d, ull a, ull b) {
    asm("fma.rn.f32x2 %0, %1, %2, %0;" : "+l"(d) : "l"(a), "l"(b));
}
__device__ __forceinline__ ull pack2(float x, float y) {
    ull r;
    asm("mov.b64 %0, {%1, %2};" : "=l"(r) : "f"(x), "f"(y));
    return r;
}
__device__ __forceinline__ float2 unpack2(ull v) {
    float2 r;
    asm("mov.b64 {%0, %1}, %2;" : "=f"(r.x), "=f"(r.y) : "l"(v));
    return r;
}
__device__ __forceinline__ unsigned f2tf(float x) {
    unsigned r;
    asm("cvt.rna.tf32.f32 %0, %1;" : "=r"(r) : "f"(x));
    return r;
}
// D(16x8,f32) += A(16x8,tf32,row) * B(8x8,tf32,col)
__device__ __forceinline__ void mma_tf32(float* d,
                                         unsigned a0, unsigned a1,
                                         unsigned a2, unsigned a3,
                                         unsigned b0, unsigned b1) {
    asm("mma.sync.aligned.m16n8k8.row.col.f32.tf32.tf32.f32 "
        "{%0,%1,%2,%3}, {%4,%5,%6,%7}, {%8,%9}, {%0,%1,%2,%3};"
        : "+f"(d[0]), "+f"(d[1]), "+f"(d[2]), "+f"(d[3])
        : "r"(a0), "r"(a1), "r"(a2), "r"(a3), "r"(b0), "r"(b1));
}

// ---------------------------------------------------------------------------
__global__ void rope_table_kernel(const int* __restrict__ sp) {
    int tid = blockIdx.x * 32 + threadIdx.x;
    if (tid >= 256) return;
    int t = tid >> 6, i = tid & 63;
    double f = exp2(-(double)i * (13.287712379549449 / 64.0));
    double ang = (double)(sp[0] + t) * f;
    double s, c;
    sincos(ang, &s, &c);
    g_cos[t][i] = (float)c;
    g_sin[t][i] = (float)s;
}

// ---------------------------------------------------------------------------
// Big GEMM (fp32 f32x2): 64 tokens x 128-col tile, K-chunk 128 (ksplit 16).
// qkv=1: fused QKV (ctile 0-15 wq, 16-19 wk, 20-23 wv). qkv=0: wa only.
// ---------------------------------------------------------------------------
__global__ void gemm_big(const float* __restrict__ X,
                         const float* __restrict__ wa,
                         const float* __restrict__ wb,
                         const float* __restrict__ wc,
                         float* __restrict__ P, int Pn, int qkv) {
    const int tid = threadIdx.x;
    const int ct = blockIdx.x, ks = blockIdx.y;
    const float* W;
    int Wn, Wc, ob;
    if (qkv) {
        if (ct < 16)      { W = wa; Wn = 2048; Wc = ct * 128;        ob = Wc; }
        else if (ct < 20) { W = wb; Wn = 512;  Wc = (ct - 16) * 128; ob = 2048 + Wc; }
        else              { W = wc; Wn = 512;  Wc = (ct - 20) * 128; ob = 2560 + Wc; }
    } else { W = wa; Wn = 2048; Wc = ct * 128; ob = Wc; }
    const int k0 = ks * 128;

    __shared__ float xs[64 * 68];
    __shared__ float ws[32 * 132];

    const int tx = tid & 15, ty = tid >> 4;
    ull acc[4][4];
#pragma unroll
    for (int i = 0; i < 4; i++)
#pragma unroll
        for (int j = 0; j < 4; j++) acc[i][j] = 0ULL;

    const int stok = tid >> 2, sj4 = tid & 3;
    const int skk = tid >> 3, scb = (tid & 7) * 16;

    for (int kt = 0; kt < 4; kt++) {
        const float* xp = X + stok * 2048 + k0 + kt * 32 + sj4 * 8;
        float4 a = *(const float4*)xp;
        float4 b4 = *(const float4*)(xp + 4);
        float* xd = xs + stok * 68 + sj4 * 16;
        *(float4*)(xd + 0)  = make_float4(a.x, a.x, a.y, a.y);
        *(float4*)(xd + 4)  = make_float4(a.z, a.z, a.w, a.w);
        *(float4*)(xd + 8)  = make_float4(b4.x, b4.x, b4.y, b4.y);
        *(float4*)(xd + 12) = make_float4(b4.z, b4.z, b4.w, b4.w);
        const float* wp = W + (size_t)(k0 + kt * 32 + skk) * Wn + Wc + scb;
        float* wd = ws + skk * 132 + scb;
#pragma unroll
        for (int i = 0; i < 4; i++)
            *(float4*)(wd + 4 * i) = *(const float4*)(wp + 4 * i);
        __syncthreads();

#pragma unroll 4
        for (int kkp = 0; kkp < 16; kkp++) {
            ulonglong2 xv[4];
#pragma unroll
            for (int i = 0; i < 4; i++)
                xv[i] = *(const ulonglong2*)(xs + (4 * ty + i) * 68 + 4 * kkp);
            ulonglong2 w0a = *(const ulonglong2*)(ws + (2 * kkp) * 132 + 4 * tx);
            ulonglong2 w0b = *(const ulonglong2*)(ws + (2 * kkp) * 132 + 64 + 4 * tx);
            ulonglong2 w1a = *(const ulonglong2*)(ws + (2 * kkp + 1) * 132 + 4 * tx);
            ulonglong2 w1b = *(const ulonglong2*)(ws + (2 * kkp + 1) * 132 + 64 + 4 * tx);
#pragma unroll
            for (int i = 0; i < 4; i++) {
                fma2(acc[i][0], xv[i].x, w0a.x);
                fma2(acc[i][1], xv[i].x, w0a.y);
                fma2(acc[i][2], xv[i].x, w0b.x);
                fma2(acc[i][3], xv[i].x, w0b.y);
                fma2(acc[i][0], xv[i].y, w1a.x);
                fma2(acc[i][1], xv[i].y, w1a.y);
                fma2(acc[i][2], xv[i].y, w1b.x);
                fma2(acc[i][3], xv[i].y, w1b.y);
            }
        }
        __syncthreads();
    }
#pragma unroll
    for (int i = 0; i < 4; i++) {
        float2 a0 = unpack2(acc[i][0]), a1 = unpack2(acc[i][1]);
        float2 a2 = unpack2(acc[i][2]), a3 = unpack2(acc[i][3]);
        float* dst = P + ((size_t)ks * 64 + 4 * ty + i) * Pn + ob + 4 * tx;
        *(float4*)dst        = make_float4(a0.x, a0.y, a1.x, a1.y);
        *(float4*)(dst + 64) = make_float4(a2.x, a2.y, a3.x, a3.y);
    }
}

// ---------------------------------------------------------------------------
__global__ void reduce_rope_kernel() {
    int gid = blockIdx.x * 256 + threadIdx.x;
    if (gid >= 64 * 1536) return;
    int token = gid / 1536;
    int r = gid - token * 1536;
    int t = token & 3;
    const float* P = &g_qkv_part[0][0][0];

    int h, i, c1;
    bool is_q = (r < 1024), is_k = (!is_q && r < 1280);
    if (is_q)      { h = r >> 6;              i = r & 63; c1 = h * 128 + i; }
    else if (is_k) { int rr = r - 1024; h = rr >> 6; i = rr & 63; c1 = 2048 + h * 128 + i; }
    else           { int rr = r - 1280; h = rr >> 6; i = rr & 63; c1 = 2560 + h * 128 + i; }

    float s1 = 0.f, s2 = 0.f;
#pragma unroll
    for (int ks = 0; ks < KSPLIT; ks++) {
        const float* row = P + ((size_t)ks * 64 + token) * 3072;
        s1 += row[c1];
        s2 += row[c1 + 64];
    }
    if (!is_q && !is_k) {
        g_v[token * 512 + h * 128 + i] = s1;
        g_v[token * 512 + h * 128 + i + 64] = s2;
        return;
    }
    float cs = g_cos[t][i], sn = g_sin[t][i];
    float o1 = s1 * cs - s2 * sn;
    float o2 = s1 * sn + s2 * cs;
    if (is_q) {
        g_q[token * 2048 + c1] = o1;
        g_q[token * 2048 + c1 + 64] = o2;
    } else {
        int cc = h * 128 + i;
        g_k[token * 512 + cc] = o1;
        g_k[token * 512 + cc + 64] = o2;
    }
}

// ---------------------------------------------------------------------------
// Attention via mma.sync m16n8k8 tf32 (fp32 accumulate).
// Pass1: S[16q][256k] = Q K^T. 8 warps x 32 keys; 4 stages of 32 d; K staged
//   into a fragment buffer (XOR-swizzled: STS.128 optimal, LDS.32 conflict-free).
// Pass2: O[16q][128d] = P V. 8 warps x 16 d; V in natural [s][132] (b-frag
//   LDS.32 banks 4c+r conflict-free); P read from at_s.
// smem floats: q_frag 2048 + at_s 16*262 + m/l 32 + kv 8448 = 14720 (58.9KB)
// ---------------------------------------------------------------------------
#define ATS 262
#define ATTN_SMEM_FLOATS (2048 + 4192 + 32 + 8448)
#define ATTN_SMEM_BYTES (ATTN_SMEM_FLOATS * 4)

__global__ void __launch_bounds__(256, 3)
attn_kernel(const float* __restrict__ ck, const float* __restrict__ cv) {
    extern __shared__ float sm[];
    float* q_frag = sm;                // [16 ksteps][128] A-fragment order
    float* at_s   = sm + 2048;         // [16][262] scores / P
    float* m_s    = at_s + 4192;       // [16]
    float* l_s    = m_s + 16;          // [16]
    float* kv_s   = l_s + 16;          // pass1 frag buffer 8192 / pass2 [64][132]

    const int tid = threadIdx.x;
    const int split = blockIdx.x % NSPLITS;
    const int pair  = blockIdx.x / NSPLITS;
    const int b = pair >> 2, kvh = pair & 3;
    const int len = (split < 8) ? 256 : 4;
    const float scale = 0.08838834764831845f;
    const int w = tid >> 5, lane = tid & 31;

    const float* cbk = ck + (size_t)(b * 4 + kvh) * 4096 * 128;
    const float* cbv = cv + (size_t)(b * 4 + kvh) * 4096 * 128;
    const float* gkb = g_k + (b * 4) * 512 + kvh * 128;
    const float* gvb = g_v + (b * 4) * 512 + kvh * 128;

    // ---- stage Q in A-fragment order (tf32-converted) ----
    // q_frag[ks*128 + tl*4 + j] = Q[row][col], row = tl/4 + (j&1)*8,
    // col = ks*8 + (tl&3) + (j>>1)*4 ; q row index = hg*4 + t.
#pragma unroll
    for (int i = 0; i < 8; i++) {
        int idx = tid + i * 256;
        int ks = idx >> 7, rem = idx & 127;
        int tl = rem >> 2, j = rem & 3;
        int row = (tl >> 2) + (j & 1) * 8;
        int col = ks * 8 + (tl & 3) + (j >> 1) * 4;
        int hg = row >> 2, t = row & 3;
        float v = g_q[(b * 4 + t) * 2048 + (kvh * 4 + hg) * 128 + col];
        q_frag[idx] = __uint_as_float(f2tf(v));
    }

    // ---- Pass 1: scores ----
    float acc[4][4];
#pragma unroll
    for (int i = 0; i < 4; i++)
#pragma unroll
        for (int j = 0; j < 4; j++) acc[i][j] = 0.f;

    const int b7 = lane & 7;
#pragma unroll 1
    for (int s = 0; s < 4; s++) {
        __syncthreads();
        // stage K slab (256 keys x 32 d) into fragment buffer
#pragma unroll
        for (int r = 0; r < 8; r++) {
            int key = w * 32 + r * 4 + (lane >> 3);
            const float* src;
            if (split < 8) {
                int se = split * 256 + key;
                int crow = (se < 4) ? se : se + 2048;
                src = cbk + (size_t)crow * 128;
            } else {
                int t = (key < 4) ? key : 0;
                src = gkb + t * 512;
            }
            float4 v = *(const float4*)(src + s * 32 + b7 * 4);
            uint4 u = make_uint4(f2tf(v.x), f2tf(v.y), f2tf(v.z), f2tf(v.w));
            int addr = ((key >> 3) << 8) + ((b7 >> 1) << 6) + ((b7 & 1) << 5)
                     + ((((key & 7) ^ b7) & 7) << 2);
            *(uint4*)(kv_s + addr) = u;
        }
        __syncthreads();

#pragma unroll
        for (int ks = 0; ks < 4; ks++) {
            uint4 A = *(const uint4*)(q_frag + (s * 4 + ks) * 128 + lane * 4);
#pragma unroll
            for (int nt = 0; nt < 4; nt++) {
                const float* fb = kv_s + (w * 4 + nt) * 256 + ks * 64;
                unsigned bb0 = __float_as_uint(
                    fb[((((lane >> 2) ^ (2 * ks)) & 7) << 2) + (lane & 3)]);
                unsigned bb1 = __float_as_uint(
                    fb[32 + ((((lane >> 2) ^ (2 * ks + 1)) & 7) << 2) + (lane & 3)]);
                mma_tf32(acc[nt], A.x, A.y, A.z, A.w, bb0, bb1);
            }
        }
    }
    // write scores to at_s
    {
        int r0 = lane >> 2, c2 = (lane & 3) * 2;
#pragma unroll
        for (int nt = 0; nt < 4; nt++) {
            int cc = w * 32 + nt * 8 + c2;
            *(float2*)(at_s + r0 * ATS + cc) =
                make_float2(acc[nt][0] * scale, acc[nt][1] * scale);
            *(float2*)(at_s + (r0 + 8) * ATS + cc) =
                make_float2(acc[nt][2] * scale, acc[nt][3] * scale);
        }
    }
    __syncthreads();

    // ---- softmax: warp w owns rows 2w, 2w+1 ; store P as tf32 ----
    {
#pragma unroll
        for (int rr = 0; rr < 2; rr++) {
            int r = w * 2 + rr;
            float* row = at_s + r * ATS;
            float m = -3.0e38f;
            for (int sx = lane; sx < len; sx += 32) m = fmaxf(m, row[sx]);
#pragma unroll
            for (int off = 16; off; off >>= 1)
                m = fmaxf(m, __shfl_xor_sync(0xffffffffu, m, off));
            float l = 0.f;
            for (int sx = lane; sx < len; sx += 32) {
                float e = __expf(row[sx] - m);
                row[sx] = __uint_as_float(f2tf(e));
                l += e;
            }
#pragma unroll
            for (int off = 16; off; off >>= 1)
                l += __shfl_xor_sync(0xffffffffu, l, off);
            for (int sx = len + lane; sx < 256; sx += 32) row[sx] = 0.f;
            if (lane == 0) { m_s[r] = m; l_s[r] = l; }
        }
    }

    // ---- Pass 2: O = P @ V ; warp w owns d cols w*16..w*16+15 ----
    float oacc[2][4];
#pragma unroll
    for (int i = 0; i < 2; i++)
#pragma unroll
        for (int j = 0; j < 4; j++) oacc[i][j] = 0.f;
    const int NT = (split < 8) ? 4 : 1;

#pragma unroll 1
    for (int tile = 0; tile < NT; tile++) {
        __syncthreads();
        // stage V tile [64][132], tf32-converted; warp w -> rows w*8..w*8+7
#pragma unroll
        for (int r = 0; r < 8; r++) {
            int lrow = w * 8 + r;
            int sl = tile * 64 + lrow;
            const float* src;
            if (split < 8) {
                int se = split * 256 + sl;
                int crow = (se < 4) ? se : se + 2048;
                src = cbv + (size_t)crow * 128;
            } else {
                int t = (sl < 4) ? sl : 0;
                src = gvb + t * 512;
            }
            float4 v = *(const float4*)(src + lane * 4);
            uint4 u = make_uint4(f2tf(v.x), f2tf(v.y), f2tf(v.z), f2tf(v.w));
            *(uint4*)(kv_s + lrow * 132 + lane * 4) = u;
        }
        __syncthreads();

#pragma unroll
        for (int j = 0; j < 8; j++) {
            int sb = tile * 64 + j * 8;
            const float* pr = at_s + (lane >> 2) * ATS + sb + (lane & 3);
            unsigned a0 = __float_as_uint(pr[0]);
            unsigned a2 = __float_as_uint(pr[4]);
            unsigned a1 = __float_as_uint(pr[8 * ATS]);
            unsigned a3 = __float_as_uint(pr[8 * ATS + 4]);
            const float* vb = kv_s + (j * 8 + (lane & 3)) * 132 + w * 16 + (lane >> 2);
#pragma unroll
            for (int nt = 0; nt < 2; nt++) {
                unsigned bb0 = __float_as_uint(vb[nt * 8]);
                unsigned bb1 = __float_as_uint(vb[4 * 132 + nt * 8]);
                mma_tf32(oacc[nt], a0, a1, a2, a3, bb0, bb1);
            }
        }
    }

    // write partials + stats
    {
        size_t base = (size_t)(pair * NSPLITS + split) * 16;
        int r0 = lane >> 2, c2 = (lane & 3) * 2;
#pragma unroll
        for (int nt = 0; nt < 2; nt++) {
            int cc = w * 16 + nt * 8 + c2;
            *(float2*)(g_po + (base + r0) * 128 + cc) =
                make_float2(oacc[nt][0], oacc[nt][1]);
            *(float2*)(g_po + (base + r0 + 8) * 128 + cc) =
                make_float2(oacc[nt][2], oacc[nt][3]);
        }
        __syncthreads();
        if (tid < 16) {
            g_pm[base + tid] = m_s[tid];
            g_pl[base + tid] = l_s[tid];
        }
    }
}

// ---------------------------------------------------------------------------
__global__ void combine_kernel() {
    int bidx = blockIdx.x;
    int pair = bidx >> 4, q = bidx & 15;
    int d = threadIdx.x;
    int hg = q >> 2, t = q & 3;
    int b = pair >> 2, kvh = pair & 3;

    float ms[NSPLITS];
    float M = -3.0e38f;
#pragma unroll
    for (int i = 0; i < NSPLITS; i++) {
        ms[i] = g_pm[(pair * NSPLITS + i) * 16 + q];
        M = fmaxf(M, ms[i]);
    }
    float L = 0.f, acc = 0.f;
#pragma unroll
    for (int i = 0; i < NSPLITS; i++) {
        float wgt = __expf(ms[i] - M);
        L += wgt * g_pl[(pair * NSPLITS + i) * 16 + q];
        acc += wgt * g_po[((size_t)(pair * NSPLITS + i) * 16 + q) * 128 + d];
    }
    g_y[(b * 4 + t) * 2048 + (kvh * 4 + hg) * 128 + d] = acc / L;
}

// ---------------------------------------------------------------------------
__global__ void reduce_out_kernel(float* __restrict__ out) {
    int gid = blockIdx.x * 256 + threadIdx.x;
    if (gid >= 64 * 2048 / 4) return;
    const float4* P = (const float4*)&g_out_part[0][0][0];
    float4 s = make_float4(0.f, 0.f, 0.f, 0.f);
#pragma unroll
    for (int ks = 0; ks < KSPLIT; ks++) {
        float4 v = P[(size_t)ks * 32768 + gid];
        s.x += v.x; s.y += v.y; s.z += v.z; s.w += v.w;
    }
    ((float4*)out)[gid] = s;
}

// ---------------------------------------------------------------------------
extern "C" void kernel_launch(void* const* d_in, const int* in_sizes, int n_in,
                              void* d_out, int out_size) {
    const float* x     = (const float*)d_in[0];
    const float* ck    = (const float*)d_in[1];
    const float* cv    = (const float*)d_in[2];
    const float* wq    = (const float*)d_in[3];
    const float* wk    = (const float*)d_in[4];
    const float* wv    = (const float*)d_in[5];
    const float* wproj = (const float*)d_in[6];
    const int*   sp    = (const int*)d_in[7];
    float* out = (float*)d_out;

    float *qkvp, *yp, *outp;
    cudaGetSymbolAddress((void**)&qkvp, g_qkv_part);
    cudaGetSymbolAddress((void**)&yp, g_y);
    cudaGetSymbolAddress((void**)&outp, g_out_part);

    cudaFuncSetAttribute(attn_kernel,
                         cudaFuncAttributeMaxDynamicSharedMemorySize,
                         ATTN_SMEM_BYTES);

    rope_table_kernel<<<8, 32>>>(sp);
    gemm_big<<<dim3(24, KSPLIT), 256>>>(x, wq, wk, wv, qkvp, 3072, 1);
    reduce_rope_kernel<<<384, 256>>>();
    attn_kernel<<<64 * NSPLITS, 256, ATTN_SMEM_BYTES>>>(ck, cv);
    combine_kernel<<<1024, 128>>>();
    gemm_big<<<dim3(16, KSPLIT), 256>>>(yp, wproj, wproj, wproj, outp, 2048, 0);
    reduce_out_kernel<<<128, 256>>>(out);
}

// round 6
// speedup vs baseline: 1.8663x; 1.0509x over previous
#include <cuda_runtime.h>
#include <math.h>

// B=16, T=4, C=2048, 16 heads / 4 kv heads, d=128, S_cache=4096,
// window=2048, sink=4 -> 2052 effective keys.
// Key s: s<4 -> cache row s ; 4<=s<2048 -> cache row s+2048 ; s>=2048 -> new.

#define QKV_KS 8     // k-split for QKV gemm (K-chunk 256)
#define PROJ_KS 16   // k-split for out-proj gemm (K-chunk 128)
#define NSPLITS 9    // 8 x 256 cached keys + 1 x 4 new keys

__device__ float g_qkv_part[QKV_KS][64][3072];
__device__ float g_q[64 * 2048];
__device__ float g_k[64 * 512];
__device__ float g_v[64 * 512];
__device__ float g_po[64 * NSPLITS * 16 * 128];
__device__ float g_pm[64 * NSPLITS * 16];
__device__ float g_pl[64 * NSPLITS * 16];
__device__ float g_y[64 * 2048];
__device__ float g_out_part[PROJ_KS][64][2048];
__device__ float g_cos[4][64];
__device__ float g_sin[4][64];

typedef unsigned long long ull;

__device__ __forceinline__ unsigned f2tf(float x) {
    unsigned r;
    asm("cvt.rna.tf32.f32 %0, %1;" : "=r"(r) : "f"(x));
    return r;
}
// D(16x8,f32) += A(16x8,tf32,row) * B(8x8,tf32,col)
__device__ __forceinline__ void mma_tf32(float* d,
                                         unsigned a0, unsigned a1,
                                         unsigned a2, unsigned a3,
                                         unsigned b0, unsigned b1) {
    asm("mma.sync.aligned.m16n8k8.row.col.f32.tf32.tf32.f32 "
        "{%0,%1,%2,%3}, {%4,%5,%6,%7}, {%8,%9}, {%0,%1,%2,%3};"
        : "+f"(d[0]), "+f"(d[1]), "+f"(d[2]), "+f"(d[3])
        : "r"(a0), "r"(a1), "r"(a2), "r"(a3), "r"(b0), "r"(b1));
}

// ---------------------------------------------------------------------------
__global__ void rope_table_kernel(const int* __restrict__ sp) {
    int tid = blockIdx.x * 32 + threadIdx.x;
    if (tid >= 256) return;
    int t = tid >> 6, i = tid & 63;
    double f = exp2(-(double)i * (13.287712379549449 / 64.0));
    double ang = (double)(sp[0] + t) * f;
    double s, c;
    sincos(ang, &s, &c);
    g_cos[t][i] = (float)c;
    g_sin[t][i] = (float)s;
}

// ---------------------------------------------------------------------------
// Tensor-core GEMM with 3-term tf32 split (near-fp32 accuracy).
// CTA: 64 tokens x 128 cols; grid y = k-split; nslab = Kchunk/32.
// Warps: w&3 -> m-tile (16 rows), w>>2 -> n-half (64 cols).
// qkv=1: ct 0-15 wq, 16-19 wk, 20-23 wv. qkv=0: wa only.
// ---------------------------------------------------------------------------
__global__ void __launch_bounds__(256)
gemm_tf32(const float* __restrict__ X,
          const float* __restrict__ wa,
          const float* __restrict__ wb,
          const float* __restrict__ wc,
          float* __restrict__ P, int Pn, int qkv, int nslab) {
    const int tid = threadIdx.x;
    const int ct = blockIdx.x, ks = blockIdx.y;
    const float* W;
    int Wn, Wc, ob;
    if (qkv) {
        if (ct < 16)      { W = wa; Wn = 2048; Wc = ct * 128;        ob = Wc; }
        else if (ct < 20) { W = wb; Wn = 512;  Wc = (ct - 16) * 128; ob = 2048 + Wc; }
        else              { W = wc; Wn = 512;  Wc = (ct - 20) * 128; ob = 2560 + Wc; }
    } else { W = wa; Wn = 2048; Wc = ct * 128; ob = Wc; }
    const int k0 = ks * nslab * 32;

    __shared__ float xf[2048];        // X slab in A-fragment order (raw fp32)
    __shared__ float ws[32 * 136];    // W slab [32 k][128 cols], pad 136

    const int w = tid >> 5, lane = tid & 31;
    const int mt = w & 3, nh = w >> 2;

    float acc[8][4];
#pragma unroll
    for (int i = 0; i < 8; i++)
#pragma unroll
        for (int j = 0; j < 4; j++) acc[i][j] = 0.f;

#pragma unroll 1
    for (int sl = 0; sl < nslab; sl++) {
        __syncthreads();
        // ---- stage W slab (coalesced, conflict-free) ----
#pragma unroll
        for (int it = 0; it < 4; it++) {
            int fid = tid + it * 256;          // float4 index, 0..1023
            int row = fid >> 5, c4 = (fid & 31) * 4;
            *(float4*)(ws + row * 136 + c4) =
                *(const float4*)(W + (size_t)(k0 + sl * 32 + row) * Wn + Wc + c4);
        }
        // ---- stage X slab in fragment order ----
#pragma unroll
        for (int bb = 0; bb < 2; bb++) {
            int blk = w * 2 + bb;              // blk = ks4*4 + mt
            int ks4 = blk >> 2, mtb = blk & 3;
            float tmp[4];
#pragma unroll
            for (int j = 0; j < 4; j++) {
                int row = mtb * 16 + (lane >> 2) + (j & 1) * 8;
                int col = ks4 * 8 + (lane & 3) + (j >> 1) * 4;
                tmp[j] = X[row * 2048 + k0 + sl * 32 + col];
            }
            *(float4*)(xf + blk * 128 + lane * 4) =
                make_float4(tmp[0], tmp[1], tmp[2], tmp[3]);
        }
        __syncthreads();

#pragma unroll
        for (int k4 = 0; k4 < 4; k4++) {
            float4 ar = *(const float4*)(xf + (k4 * 4 + mt) * 128 + lane * 4);
            unsigned ah0 = f2tf(ar.x), ah1 = f2tf(ar.y);
            unsigned ah2 = f2tf(ar.z), ah3 = f2tf(ar.w);
            unsigned al0 = f2tf(ar.x - __uint_as_float(ah0));
            unsigned al1 = f2tf(ar.y - __uint_as_float(ah1));
            unsigned al2 = f2tf(ar.z - __uint_as_float(ah2));
            unsigned al3 = f2tf(ar.w - __uint_as_float(ah3));
            const float* wbase = ws + (k4 * 8 + (lane & 3)) * 136
                               + nh * 64 + (lane >> 2);
#pragma unroll
            for (int nt = 0; nt < 8; nt++) {
                float b0 = wbase[nt * 8];
                float b1 = wbase[nt * 8 + 4 * 136];
                unsigned bh0 = f2tf(b0), bh1 = f2tf(b1);
                unsigned bl0 = f2tf(b0 - __uint_as_float(bh0));
                unsigned bl1 = f2tf(b1 - __uint_as_float(bh1));
                mma_tf32(acc[nt], ah0, ah1, ah2, ah3, bh0, bh1);
                mma_tf32(acc[nt], ah0, ah1, ah2, ah3, bl0, bl1);
                mma_tf32(acc[nt], al0, al1, al2, al3, bh0, bh1);
            }
        }
    }
    // ---- epilogue ----
    {
        int r = lane >> 2, c2 = (lane & 3) * 2;
#pragma unroll
        for (int nt = 0; nt < 8; nt++) {
            int col = ob + nh * 64 + nt * 8 + c2;
            *(float2*)(P + ((size_t)ks * 64 + mt * 16 + r) * Pn + col) =
                make_float2(acc[nt][0], acc[nt][1]);
            *(float2*)(P + ((size_t)ks * 64 + mt * 16 + r + 8) * Pn + col) =
                make_float2(acc[nt][2], acc[nt][3]);
        }
    }
}

// ---------------------------------------------------------------------------
__global__ void reduce_rope_kernel() {
    int gid = blockIdx.x * 256 + threadIdx.x;
    if (gid >= 64 * 1536) return;
    int token = gid / 1536;
    int r = gid - token * 1536;
    int t = token & 3;
    const float* P = &g_qkv_part[0][0][0];

    int h, i, c1;
    bool is_q = (r < 1024), is_k = (!is_q && r < 1280);
    if (is_q)      { h = r >> 6;              i = r & 63; c1 = h * 128 + i; }
    else if (is_k) { int rr = r - 1024; h = rr >> 6; i = rr & 63; c1 = 2048 + h * 128 + i; }
    else           { int rr = r - 1280; h = rr >> 6; i = rr & 63; c1 = 2560 + h * 128 + i; }

    float s1 = 0.f, s2 = 0.f;
#pragma unroll
    for (int ks = 0; ks < QKV_KS; ks++) {
        const float* row = P + ((size_t)ks * 64 + token) * 3072;
        s1 += row[c1];
        s2 += row[c1 + 64];
    }
    if (!is_q && !is_k) {
        g_v[token * 512 + h * 128 + i] = s1;
        g_v[token * 512 + h * 128 + i + 64] = s2;
        return;
    }
    float cs = g_cos[t][i], sn = g_sin[t][i];
    float o1 = s1 * cs - s2 * sn;
    float o2 = s1 * sn + s2 * cs;
    if (is_q) {
        g_q[token * 2048 + c1] = o1;
        g_q[token * 2048 + c1 + 64] = o2;
    } else {
        int cc = h * 128 + i;
        g_k[token * 512 + cc] = o1;
        g_k[token * 512 + cc + 64] = o2;
    }
}

// ---------------------------------------------------------------------------
// Attention via mma.sync m16n8k8 tf32 (unchanged from R5: 45us, proven).
// ---------------------------------------------------------------------------
#define ATS 262
#define ATTN_SMEM_FLOATS (2048 + 4192 + 32 + 8448)
#define ATTN_SMEM_BYTES (ATTN_SMEM_FLOATS * 4)

__global__ void __launch_bounds__(256, 3)
attn_kernel(const float* __restrict__ ck, const float* __restrict__ cv) {
    extern __shared__ float sm[];
    float* q_frag = sm;                // [16 ksteps][128] A-fragment order
    float* at_s   = sm + 2048;         // [16][262] scores / P
    float* m_s    = at_s + 4192;       // [16]
    float* l_s    = m_s + 16;          // [16]
    float* kv_s   = l_s + 16;          // pass1 frag buffer 8192 / pass2 [64][132]

    const int tid = threadIdx.x;
    const int split = blockIdx.x % NSPLITS;
    const int pair  = blockIdx.x / NSPLITS;
    const int b = pair >> 2, kvh = pair & 3;
    const int len = (split < 8) ? 256 : 4;
    const float scale = 0.08838834764831845f;
    const int w = tid >> 5, lane = tid & 31;

    const float* cbk = ck + (size_t)(b * 4 + kvh) * 4096 * 128;
    const float* cbv = cv + (size_t)(b * 4 + kvh) * 4096 * 128;
    const float* gkb = g_k + (b * 4) * 512 + kvh * 128;
    const float* gvb = g_v + (b * 4) * 512 + kvh * 128;

    // ---- stage Q in A-fragment order (tf32-converted) ----
#pragma unroll
    for (int i = 0; i < 8; i++) {
        int idx = tid + i * 256;
        int ks = idx >> 7, rem = idx & 127;
        int tl = rem >> 2, j = rem & 3;
        int row = (tl >> 2) + (j & 1) * 8;
        int col = ks * 8 + (tl & 3) + (j >> 1) * 4;
        int hg = row >> 2, t = row & 3;
        float v = g_q[(b * 4 + t) * 2048 + (kvh * 4 + hg) * 128 + col];
        q_frag[idx] = __uint_as_float(f2tf(v));
    }

    // ---- Pass 1: scores ----
    float acc[4][4];
#pragma unroll
    for (int i = 0; i < 4; i++)
#pragma unroll
        for (int j = 0; j < 4; j++) acc[i][j] = 0.f;

    const int b7 = lane & 7;
#pragma unroll 1
    for (int s = 0; s < 4; s++) {
        __syncthreads();
#pragma unroll
        for (int r = 0; r < 8; r++) {
            int key = w * 32 + r * 4 + (lane >> 3);
            const float* src;
            if (split < 8) {
                int se = split * 256 + key;
                int crow = (se < 4) ? se : se + 2048;
                src = cbk + (size_t)crow * 128;
            } else {
                int t = (key < 4) ? key : 0;
                src = gkb + t * 512;
            }
            float4 v = *(const float4*)(src + s * 32 + b7 * 4);
            uint4 u = make_uint4(f2tf(v.x), f2tf(v.y), f2tf(v.z), f2tf(v.w));
            int addr = ((key >> 3) << 8) + ((b7 >> 1) << 6) + ((b7 & 1) << 5)
                     + ((((key & 7) ^ b7) & 7) << 2);
            *(uint4*)(kv_s + addr) = u;
        }
        __syncthreads();

#pragma unroll
        for (int ks = 0; ks < 4; ks++) {
            uint4 A = *(const uint4*)(q_frag + (s * 4 + ks) * 128 + lane * 4);
#pragma unroll
            for (int nt = 0; nt < 4; nt++) {
                const float* fb = kv_s + (w * 4 + nt) * 256 + ks * 64;
                unsigned bb0 = __float_as_uint(
                    fb[((((lane >> 2) ^ (2 * ks)) & 7) << 2) + (lane & 3)]);
                unsigned bb1 = __float_as_uint(
                    fb[32 + ((((lane >> 2) ^ (2 * ks + 1)) & 7) << 2) + (lane & 3)]);
                mma_tf32(acc[nt], A.x, A.y, A.z, A.w, bb0, bb1);
            }
        }
    }
    {
        int r0 = lane >> 2, c2 = (lane & 3) * 2;
#pragma unroll
        for (int nt = 0; nt < 4; nt++) {
            int cc = w * 32 + nt * 8 + c2;
            *(float2*)(at_s + r0 * ATS + cc) =
                make_float2(acc[nt][0] * scale, acc[nt][1] * scale);
            *(float2*)(at_s + (r0 + 8) * ATS + cc) =
                make_float2(acc[nt][2] * scale, acc[nt][3] * scale);
        }
    }
    __syncthreads();

    // ---- softmax: warp w owns rows 2w, 2w+1 ; store P as tf32 ----
    {
#pragma unroll
        for (int rr = 0; rr < 2; rr++) {
            int r = w * 2 + rr;
            float* row = at_s + r * ATS;
            float m = -3.0e38f;
            for (int sx = lane; sx < len; sx += 32) m = fmaxf(m, row[sx]);
#pragma unroll
            for (int off = 16; off; off >>= 1)
                m = fmaxf(m, __shfl_xor_sync(0xffffffffu, m, off));
            float l = 0.f;
            for (int sx = lane; sx < len; sx += 32) {
                float e = __expf(row[sx] - m);
                row[sx] = __uint_as_float(f2tf(e));
                l += e;
            }
#pragma unroll
            for (int off = 16; off; off >>= 1)
                l += __shfl_xor_sync(0xffffffffu, l, off);
            for (int sx = len + lane; sx < 256; sx += 32) row[sx] = 0.f;
            if (lane == 0) { m_s[r] = m; l_s[r] = l; }
        }
    }

    // ---- Pass 2: O = P @ V ; warp w owns d cols w*16..w*16+15 ----
    float oacc[2][4];
#pragma unroll
    for (int i = 0; i < 2; i++)
#pragma unroll
        for (int j = 0; j < 4; j++) oacc[i][j] = 0.f;
    const int NT = (split < 8) ? 4 : 1;

#pragma unroll 1
    for (int tile = 0; tile < NT; tile++) {
        __syncthreads();
#pragma unroll
        for (int r = 0; r < 8; r++) {
            int lrow = w * 8 + r;
            int sl = tile * 64 + lrow;
            const float* src;
            if (split < 8) {
                int se = split * 256 + sl;
                int crow = (se < 4) ? se : se + 2048;
                src = cbv + (size_t)crow * 128;
            } else {
                int t = (sl < 4) ? sl : 0;
                src = gvb + t * 512;
            }
            float4 v = *(const float4*)(src + lane * 4);
            uint4 u = make_uint4(f2tf(v.x), f2tf(v.y), f2tf(v.z), f2tf(v.w));
            *(uint4*)(kv_s + lrow * 132 + lane * 4) = u;
        }
        __syncthreads();

#pragma unroll
        for (int j = 0; j < 8; j++) {
            int sb = tile * 64 + j * 8;
            const float* pr = at_s + (lane >> 2) * ATS + sb + (lane & 3);
            unsigned a0 = __float_as_uint(pr[0]);
            unsigned a2 = __float_as_uint(pr[4]);
            unsigned a1 = __float_as_uint(pr[8 * ATS]);
            unsigned a3 = __float_as_uint(pr[8 * ATS + 4]);
            const float* vb = kv_s + (j * 8 + (lane & 3)) * 132 + w * 16 + (lane >> 2);
#pragma unroll
            for (int nt = 0; nt < 2; nt++) {
                unsigned bb0 = __float_as_uint(vb[nt * 8]);
                unsigned bb1 = __float_as_uint(vb[4 * 132 + nt * 8]);
                mma_tf32(oacc[nt], a0, a1, a2, a3, bb0, bb1);
            }
        }
    }

    {
        size_t base = (size_t)(pair * NSPLITS + split) * 16;
        int r0 = lane >> 2, c2 = (lane & 3) * 2;
#pragma unroll
        for (int nt = 0; nt < 2; nt++) {
            int cc = w * 16 + nt * 8 + c2;
            *(float2*)(g_po + (base + r0) * 128 + cc) =
                make_float2(oacc[nt][0], oacc[nt][1]);
            *(float2*)(g_po + (base + r0 + 8) * 128 + cc) =
                make_float2(oacc[nt][2], oacc[nt][3]);
        }
        __syncthreads();
        if (tid < 16) {
            g_pm[base + tid] = m_s[tid];
            g_pl[base + tid] = l_s[tid];
        }
    }
}

// ---------------------------------------------------------------------------
__global__ void combine_kernel() {
    int bidx = blockIdx.x;
    int pair = bidx >> 4, q = bidx & 15;
    int d = threadIdx.x;
    int hg = q >> 2, t = q & 3;
    int b = pair >> 2, kvh = pair & 3;

    float ms[NSPLITS];
    float M = -3.0e38f;
#pragma unroll
    for (int i = 0; i < NSPLITS; i++) {
        ms[i] = g_pm[(pair * NSPLITS + i) * 16 + q];
        M = fmaxf(M, ms[i]);
    }
    float L = 0.f, acc = 0.f;
#pragma unroll
    for (int i = 0; i < NSPLITS; i++) {
        float wgt = __expf(ms[i] - M);
        L += wgt * g_pl[(pair * NSPLITS + i) * 16 + q];
        acc += wgt * g_po[((size_t)(pair * NSPLITS + i) * 16 + q) * 128 + d];
    }
    g_y[(b * 4 + t) * 2048 + (kvh * 4 + hg) * 128 + d] = acc / L;
}

// ---------------------------------------------------------------------------
__global__ void reduce_out_kernel(float* __restrict__ out) {
    int gid = blockIdx.x * 256 + threadIdx.x;
    if (gid >= 64 * 2048 / 4) return;
    const float4* P = (const float4*)&g_out_part[0][0][0];
    float4 s = make_float4(0.f, 0.f, 0.f, 0.f);
#pragma unroll
    for (int ks = 0; ks < PROJ_KS; ks++) {
        float4 v = P[(size_t)ks * 32768 + gid];
        s.x += v.x; s.y += v.y; s.z += v.z; s.w += v.w;
    }
    ((float4*)out)[gid] = s;
}

// ---------------------------------------------------------------------------
extern "C" void kernel_launch(void* const* d_in, const int* in_sizes, int n_in,
                              void* d_out, int out_size) {
    const float* x     = (const float*)d_in[0];
    const float* ck    = (const float*)d_in[1];
    const float* cv    = (const float*)d_in[2];
    const float* wq    = (const float*)d_in[3];
    const float* wk    = (const float*)d_in[4];
    const float* wv    = (const float*)d_in[5];
    const float* wproj = (const float*)d_in[6];
    const int*   sp    = (const int*)d_in[7];
    float* out = (float*)d_out;

    float *qkvp, *yp, *outp;
    cudaGetSymbolAddress((void**)&qkvp, g_qkv_part);
    cudaGetSymbolAddress((void**)&yp, g_y);
    cudaGetSymbolAddress((void**)&outp, g_out_part);

    cudaFuncSetAttribute(attn_kernel,
                         cudaFuncAttributeMaxDynamicSharedMemorySize,
                         ATTN_SMEM_BYTES);

    rope_table_kernel<<<8, 32>>>(sp);
    // QKV: 24 col-tiles x ksplit 8 (K-chunk 256 = 8 slabs)
    gemm_tf32<<<dim3(24, QKV_KS), 256>>>(x, wq, wk, wv, qkvp, 3072, 1, 8);
    reduce_rope_kernel<<<384, 256>>>();
    attn_kernel<<<64 * NSPLITS, 256, ATTN_SMEM_BYTES>>>(ck, cv);
    combine_kernel<<<1024, 128>>>();
    // Proj: 16 col-tiles x ksplit 16 (K-chunk 128 = 4 slabs)
    gemm_tf32<<<dim3(16, PROJ_KS), 256>>>(yp, wproj, wproj, wproj, outp, 2048, 0, 4);
    reduce_out_kernel<<<128, 256>>>(out);
}

// round 7
// speedup vs baseline: 2.0230x; 1.0839x over previous
#include <cuda_runtime.h>
#include <math.h>

// B=16, T=4, C=2048, 16 heads / 4 kv heads, d=128, S_cache=4096,
// window=2048, sink=4 -> 2052 effective keys.
// Key s: s<4 -> cache row s ; 4<=s<2048 -> cache row s+2048 ; s>=2048 -> new.

#define QKV_KS 16    // k-split for QKV gemm (K-chunk 128, 4 slabs)
#define PROJ_KS 16   // k-split for out-proj gemm (K-chunk 128, 4 slabs)
#define NSPLITS 9    // 8 x 256 cached keys + 1 x 4 new keys

__device__ float g_qkv_part[QKV_KS][64][3072];
__device__ float g_q[64 * 2048];
__device__ float g_k[64 * 512];
__device__ float g_v[64 * 512];
__device__ float g_po[64 * NSPLITS * 16 * 128];
__device__ float g_pm[64 * NSPLITS * 16];
__device__ float g_pl[64 * NSPLITS * 16];
__device__ float g_y[64 * 2048];
__device__ float g_out_part[PROJ_KS][64][2048];
__device__ float g_cos[4][64];
__device__ float g_sin[4][64];

__device__ __forceinline__ unsigned f2tf(float x) {
    unsigned r;
    asm("cvt.rna.tf32.f32 %0, %1;" : "=r"(r) : "f"(x));
    return r;
}
__device__ __forceinline__ void mma_tf32(float* d,
                                         unsigned a0, unsigned a1,
                                         unsigned a2, unsigned a3,
                                         unsigned b0, unsigned b1) {
    asm("mma.sync.aligned.m16n8k8.row.col.f32.tf32.tf32.f32 "
        "{%0,%1,%2,%3}, {%4,%5,%6,%7}, {%8,%9}, {%0,%1,%2,%3};"
        : "+f"(d[0]), "+f"(d[1]), "+f"(d[2]), "+f"(d[3])
        : "r"(a0), "r"(a1), "r"(a2), "r"(a3), "r"(b0), "r"(b1));
}
__device__ __forceinline__ unsigned sptr(const void* p) {
    return (unsigned)__cvta_generic_to_shared(p);
}
#define CPA16(dst, src) \
    asm volatile("cp.async.cg.shared.global [%0], [%1], 16;" :: "r"(dst), "l"(src))
#define CPC() asm volatile("cp.async.commit_group;")
#define CPW1() asm volatile("cp.async.wait_group 1;")
#define CPW0() asm volatile("cp.async.wait_group 0;")

// ---------------------------------------------------------------------------
__global__ void rope_table_kernel(const int* __restrict__ sp) {
    int tid = blockIdx.x * 32 + threadIdx.x;
    if (tid >= 256) return;
    int t = tid >> 6, i = tid & 63;
    double f = exp2(-(double)i * (13.287712379549449 / 64.0));
    double ang = (double)(sp[0] + t) * f;
    double s, c;
    sincos(ang, &s, &c);
    g_cos[t][i] = (float)c;
    g_sin[t][i] = (float)s;
}

// ---------------------------------------------------------------------------
// Tensor-core GEMM, 3-term tf32 split, cp.async double-buffered W slabs.
// CTA: 64 tokens x 128 cols; nslab = Kchunk/32 = 4.
// ---------------------------------------------------------------------------
__global__ void __launch_bounds__(256)
gemm_tf32(const float* __restrict__ X,
          const float* __restrict__ wa,
          const float* __restrict__ wb,
          const float* __restrict__ wc,
          float* __restrict__ P, int Pn, int qkv, int nslab) {
    const int tid = threadIdx.x;
    const int ct = blockIdx.x, ks = blockIdx.y;
    const float* W;
    int Wn, Wc, ob;
    if (qkv) {
        if (ct < 16)      { W = wa; Wn = 2048; Wc = ct * 128;        ob = Wc; }
        else if (ct < 20) { W = wb; Wn = 512;  Wc = (ct - 16) * 128; ob = 2048 + Wc; }
        else              { W = wc; Wn = 512;  Wc = (ct - 20) * 128; ob = 2560 + Wc; }
    } else { W = wa; Wn = 2048; Wc = ct * 128; ob = Wc; }
    const int k0 = ks * nslab * 32;

    __shared__ float xf[2048];           // X slab, fragment order, raw fp32
    __shared__ float ws[2][32 * 136];    // W slabs (double-buffered, raw)

    const int w = tid >> 5, lane = tid & 31;
    const int mt = w & 3, nh = w >> 2;

    float acc[8][4];
#pragma unroll
    for (int i = 0; i < 8; i++)
#pragma unroll
        for (int j = 0; j < 4; j++) acc[i][j] = 0.f;

    // W staging geometry (per thread: 4 x 16B)
    const int srow[4] = { tid >> 5, (tid + 256) >> 5, (tid + 512) >> 5, (tid + 768) >> 5 };
    const int sc4 = (tid & 31) * 4;

    // prologue: prefetch W slab 0 and 1
#pragma unroll
    for (int it = 0; it < 4; it++)
        CPA16(sptr(&ws[0][srow[it] * 136 + sc4]),
              W + (size_t)(k0 + srow[it]) * Wn + Wc + sc4);
    CPC();
    if (nslab > 1) {
#pragma unroll
        for (int it = 0; it < 4; it++)
            CPA16(sptr(&ws[1][srow[it] * 136 + sc4]),
                  W + (size_t)(k0 + 32 + srow[it]) * Wn + Wc + sc4);
        CPC();
    }

#pragma unroll 1
    for (int sl = 0; sl < nslab; sl++) {
        if (sl + 1 < nslab) CPW1(); else CPW0();
        __syncthreads();
        // ---- stage X slab in fragment order (raw fp32) ----
#pragma unroll
        for (int bb = 0; bb < 2; bb++) {
            int blk = w * 2 + bb;
            int ks4 = blk >> 2, mtb = blk & 3;
            float tmp[4];
#pragma unroll
            for (int j = 0; j < 4; j++) {
                int row = mtb * 16 + (lane >> 2) + (j & 1) * 8;
                int col = ks4 * 8 + (lane & 3) + (j >> 1) * 4;
                tmp[j] = X[row * 2048 + k0 + sl * 32 + col];
            }
            *(float4*)(xf + blk * 128 + lane * 4) =
                make_float4(tmp[0], tmp[1], tmp[2], tmp[3]);
        }
        __syncthreads();

        const float* wsl = ws[sl & 1];
#pragma unroll
        for (int k4 = 0; k4 < 4; k4++) {
            float4 ar = *(const float4*)(xf + (k4 * 4 + mt) * 128 + lane * 4);
            unsigned ah0 = f2tf(ar.x), ah1 = f2tf(ar.y);
            unsigned ah2 = f2tf(ar.z), ah3 = f2tf(ar.w);
            unsigned al0 = f2tf(ar.x - __uint_as_float(ah0));
            unsigned al1 = f2tf(ar.y - __uint_as_float(ah1));
            unsigned al2 = f2tf(ar.z - __uint_as_float(ah2));
            unsigned al3 = f2tf(ar.w - __uint_as_float(ah3));
            const float* wbase = wsl + (k4 * 8 + (lane & 3)) * 136
                               + nh * 64 + (lane >> 2);
#pragma unroll
            for (int nt = 0; nt < 8; nt++) {
                float b0 = wbase[nt * 8];
                float b1 = wbase[nt * 8 + 4 * 136];
                unsigned bh0 = f2tf(b0), bh1 = f2tf(b1);
                unsigned bl0 = f2tf(b0 - __uint_as_float(bh0));
                unsigned bl1 = f2tf(b1 - __uint_as_float(bh1));
                mma_tf32(acc[nt], ah0, ah1, ah2, ah3, bh0, bh1);
                mma_tf32(acc[nt], ah0, ah1, ah2, ah3, bl0, bl1);
                mma_tf32(acc[nt], al0, al1, al2, al3, bh0, bh1);
            }
        }
        __syncthreads();
        if (sl + 2 < nslab) {
#pragma unroll
            for (int it = 0; it < 4; it++)
                CPA16(sptr(&ws[sl & 1][srow[it] * 136 + sc4]),
                      W + (size_t)(k0 + (sl + 2) * 32 + srow[it]) * Wn + Wc + sc4);
            CPC();
        }
    }
    // ---- epilogue ----
    {
        int r = lane >> 2, c2 = (lane & 3) * 2;
#pragma unroll
        for (int nt = 0; nt < 8; nt++) {
            int col = ob + nh * 64 + nt * 8 + c2;
            *(float2*)(P + ((size_t)ks * 64 + mt * 16 + r) * Pn + col) =
                make_float2(acc[nt][0], acc[nt][1]);
            *(float2*)(P + ((size_t)ks * 64 + mt * 16 + r + 8) * Pn + col) =
                make_float2(acc[nt][2], acc[nt][3]);
        }
    }
}

// ---------------------------------------------------------------------------
__global__ void reduce_rope_kernel() {
    int gid = blockIdx.x * 256 + threadIdx.x;
    if (gid >= 64 * 1536) return;
    int token = gid / 1536;
    int r = gid - token * 1536;
    int t = token & 3;
    const float* P = &g_qkv_part[0][0][0];

    int h, i, c1;
    bool is_q = (r < 1024), is_k = (!is_q && r < 1280);
    if (is_q)      { h = r >> 6;              i = r & 63; c1 = h * 128 + i; }
    else if (is_k) { int rr = r - 1024; h = rr >> 6; i = rr & 63; c1 = 2048 + h * 128 + i; }
    else           { int rr = r - 1280; h = rr >> 6; i = rr & 63; c1 = 2560 + h * 128 + i; }

    float s1 = 0.f, s2 = 0.f;
#pragma unroll
    for (int ks = 0; ks < QKV_KS; ks++) {
        const float* row = P + ((size_t)ks * 64 + token) * 3072;
        s1 += row[c1];
        s2 += row[c1 + 64];
    }
    if (!is_q && !is_k) {
        g_v[token * 512 + h * 128 + i] = s1;
        g_v[token * 512 + h * 128 + i + 64] = s2;
        return;
    }
    float cs = g_cos[t][i], sn = g_sin[t][i];
    float o1 = s1 * cs - s2 * sn;
    float o2 = s1 * sn + s2 * cs;
    if (is_q) {
        g_q[token * 2048 + c1] = o1;
        g_q[token * 2048 + c1 + 64] = o2;
    } else {
        int cc = h * 128 + i;
        g_k[token * 512 + cc] = o1;
        g_k[token * 512 + cc + 64] = o2;
    }
}

// ---------------------------------------------------------------------------
// Attention, mma tf32, fully async KV streaming (cp.async double-buffered).
// Pass1: 8 slabs of 16 d over 256 keys; fragment-layout K buffers 2x4096.
// Pass2: 8 tiles of 32 V rows [32][136] (conflict-free), buffers 2x4352.
// smem: q_frag 2048 + at_s 4192 + m/l 32 + kv 8704 = 14976 floats (59.9KB)
// ---------------------------------------------------------------------------
#define ATS 262
#define ATTN_SMEM_FLOATS (2048 + 4192 + 32 + 8704)
#define ATTN_SMEM_BYTES (ATTN_SMEM_FLOATS * 4)

__global__ void __launch_bounds__(256, 3)
attn_kernel(const float* __restrict__ ck, const float* __restrict__ cv) {
    extern __shared__ float sm[];
    float* q_frag = sm;                // [16 ksteps][128]
    float* at_s   = sm + 2048;         // [16][262]
    float* m_s    = at_s + 4192;
    float* l_s    = m_s + 16;
    float* kv_s   = l_s + 16;          // K: 2x4096 ; V: 2x4352

    const int tid = threadIdx.x;
    const int split = blockIdx.x % NSPLITS;
    const int pair  = blockIdx.x / NSPLITS;
    const int b = pair >> 2, kvh = pair & 3;
    const int len = (split < 8) ? 256 : 4;
    const float scale = 0.08838834764831845f;
    const int w = tid >> 5, lane = tid & 31;

    const float* cbk = ck + (size_t)(b * 4 + kvh) * 4096 * 128;
    const float* cbv = cv + (size_t)(b * 4 + kvh) * 4096 * 128;
    const float* gkb = g_k + (b * 4) * 512 + kvh * 128;
    const float* gvb = g_v + (b * 4) * 512 + kvh * 128;

    // ---- pass1 staging geometry: thread covers key(w,r), quad q=lane&3 ----
    const int q4 = lane & 3;
    const float* kp[4];
    unsigned kdst[4];
#pragma unroll
    for (int r = 0; r < 4; r++) {
        int key = w * 32 + r * 8 + (lane >> 2);
        const float* src;
        if (split < 8) {
            int se = split * 256 + key;
            int crow = (se < 4) ? se : se + 2048;
            src = cbk + (size_t)crow * 128;
        } else {
            int t = (key < 4) ? key : 0;
            src = gkb + t * 512;
        }
        kp[r] = src + q4 * 4;
        int off = (w * 4 + r) * 128 + (q4 >> 1) * 64 + (q4 & 1) * 32
                + (((lane >> 2) ^ q4) & 7) * 4;
        kdst[r] = sptr(kv_s + off);
    }

    // prefetch K slabs 0,1
#pragma unroll
    for (int r = 0; r < 4; r++) CPA16(kdst[r], kp[r]);
    CPC();
#pragma unroll
    for (int r = 0; r < 4; r++) CPA16(kdst[r] + 16384, kp[r] + 16);
    CPC();

    // ---- stage Q in A-fragment order (tf32) — overlaps K DMA ----
#pragma unroll
    for (int i = 0; i < 8; i++) {
        int idx = tid + i * 256;
        int ks = idx >> 7, rem = idx & 127;
        int tl = rem >> 2, j = rem & 3;
        int row = (tl >> 2) + (j & 1) * 8;
        int col = ks * 8 + (tl & 3) + (j >> 1) * 4;
        int hg = row >> 2, t = row & 3;
        float v = g_q[(b * 4 + t) * 2048 + (kvh * 4 + hg) * 128 + col];
        q_frag[idx] = __uint_as_float(f2tf(v));
    }

    // ---- Pass 1 ----
    float acc[4][4];
#pragma unroll
    for (int i = 0; i < 4; i++)
#pragma unroll
        for (int j = 0; j < 4; j++) acc[i][j] = 0.f;

#pragma unroll 1
    for (int s = 0; s < 8; s++) {
        if (s < 7) CPW1(); else CPW0();
        __syncthreads();
        const float* kb = kv_s + (s & 1) * 4096;
#pragma unroll
        for (int ksl = 0; ksl < 2; ksl++) {
            uint4 A = *(const uint4*)(q_frag + (s * 2 + ksl) * 128 + lane * 4);
#pragma unroll
            for (int nt = 0; nt < 4; nt++) {
                const float* fb = kb + (w * 4 + nt) * 128 + ksl * 64;
                unsigned bb0 = f2tf(
                    fb[((((lane >> 2) ^ (2 * ksl)) & 7) << 2) + (lane & 3)]);
                unsigned bb1 = f2tf(
                    fb[32 + ((((lane >> 2) ^ (2 * ksl + 1)) & 7) << 2) + (lane & 3)]);
                mma_tf32(acc[nt], A.x, A.y, A.z, A.w, bb0, bb1);
            }
        }
        __syncthreads();
        if (s + 2 < 8) {
#pragma unroll
            for (int r = 0; r < 4; r++)
                CPA16(kdst[r] + (s & 1) * 16384, kp[r] + (s + 2) * 16);
            CPC();
        }
    }
    // write scores
    {
        int r0 = lane >> 2, c2 = (lane & 3) * 2;
#pragma unroll
        for (int nt = 0; nt < 4; nt++) {
            int cc = w * 32 + nt * 8 + c2;
            *(float2*)(at_s + r0 * ATS + cc) =
                make_float2(acc[nt][0] * scale, acc[nt][1] * scale);
            *(float2*)(at_s + (r0 + 8) * ATS + cc) =
                make_float2(acc[nt][2] * scale, acc[nt][3] * scale);
        }
    }
    __syncthreads();   // scores visible; all K-buffer reads complete

    // ---- issue V tiles 0 (and 1) — DMA overlaps softmax ----
    const int NT2 = (split < 8) ? 8 : 1;
#pragma unroll
    for (int rr = 0; rr < 4; rr++) {
        int sl = w * 4 + rr;   // tile 0
        const float* src;
        if (split < 8) {
            int se = split * 256 + sl;
            int crow = (se < 4) ? se : se + 2048;
            src = cbv + (size_t)crow * 128;
        } else {
            int t = (sl < 4) ? sl : 0;
            src = gvb + t * 512;
        }
        CPA16(sptr(kv_s + (w * 4 + rr) * 136 + lane * 4), src + lane * 4);
    }
    CPC();
    if (NT2 > 1) {
#pragma unroll
        for (int rr = 0; rr < 4; rr++) {
            int sl = 32 + w * 4 + rr;   // tile 1
            int se = split * 256 + sl;
            int crow = (se < 4) ? se : se + 2048;
            const float* src = cbv + (size_t)crow * 128;
            CPA16(sptr(kv_s + 4352 + (w * 4 + rr) * 136 + lane * 4), src + lane * 4);
        }
        CPC();
    }

    // ---- softmax: warp w owns rows 2w, 2w+1 ; store P as tf32 ----
    {
#pragma unroll
        for (int rr = 0; rr < 2; rr++) {
            int r = w * 2 + rr;
            float* row = at_s + r * ATS;
            float m = -3.0e38f;
            for (int sx = lane; sx < len; sx += 32) m = fmaxf(m, row[sx]);
#pragma unroll
            for (int off = 16; off; off >>= 1)
                m = fmaxf(m, __shfl_xor_sync(0xffffffffu, m, off));
            float l = 0.f;
            for (int sx = lane; sx < len; sx += 32) {
                float e = __expf(row[sx] - m);
                row[sx] = __uint_as_float(f2tf(e));
                l += e;
            }
#pragma unroll
            for (int off = 16; off; off >>= 1)
                l += __shfl_xor_sync(0xffffffffu, l, off);
            for (int sx = len + lane; sx < 256; sx += 32) row[sx] = 0.f;
            if (lane == 0) { m_s[r] = m; l_s[r] = l; }
        }
    }

    // ---- Pass 2: O = P @ V ----
    float oacc[2][4];
#pragma unroll
    for (int i = 0; i < 2; i++)
#pragma unroll
        for (int j = 0; j < 4; j++) oacc[i][j] = 0.f;

#pragma unroll 1
    for (int t = 0; t < NT2; t++) {
        if (t < NT2 - 1) CPW1(); else CPW0();
        __syncthreads();
        const float* vb = kv_s + (t & 1) * 4352;
#pragma unroll
        for (int j = 0; j < 4; j++) {
            const float* pr = at_s + (lane >> 2) * ATS + t * 32 + j * 8 + (lane & 3);
            unsigned a0 = __float_as_uint(pr[0]);
            unsigned a2 = __float_as_uint(pr[4]);
            unsigned a1 = __float_as_uint(pr[8 * ATS]);
            unsigned a3 = __float_as_uint(pr[8 * ATS + 4]);
            const float* vp = vb + (j * 8 + (lane & 3)) * 136 + w * 16 + (lane >> 2);
#pragma unroll
            for (int nt = 0; nt < 2; nt++) {
                unsigned bb0 = f2tf(vp[nt * 8]);
                unsigned bb1 = f2tf(vp[4 * 136 + nt * 8]);
                mma_tf32(oacc[nt], a0, a1, a2, a3, bb0, bb1);
            }
        }
        __syncthreads();
        if (t + 2 < NT2) {
#pragma unroll
            for (int rr = 0; rr < 4; rr++) {
                int sl = (t + 2) * 32 + w * 4 + rr;
                int se = split * 256 + sl;
                int crow = (se < 4) ? se : se + 2048;
                const float* src = cbv + (size_t)crow * 128;
                CPA16(sptr(kv_s + (t & 1) * 4352 + (w * 4 + rr) * 136 + lane * 4),
                      src + lane * 4);
            }
            CPC();
        }
    }

    // write partials + stats
    {
        size_t base = (size_t)(pair * NSPLITS + split) * 16;
        int r0 = lane >> 2, c2 = (lane & 3) * 2;
#pragma unroll
        for (int nt = 0; nt < 2; nt++) {
            int cc = w * 16 + nt * 8 + c2;
            *(float2*)(g_po + (base + r0) * 128 + cc) =
                make_float2(oacc[nt][0], oacc[nt][1]);
            *(float2*)(g_po + (base + r0 + 8) * 128 + cc) =
                make_float2(oacc[nt][2], oacc[nt][3]);
        }
        if (tid < 16) {
            g_pm[base + tid] = m_s[tid];
            g_pl[base + tid] = l_s[tid];
        }
    }
}

// ---------------------------------------------------------------------------
__global__ void combine_kernel() {
    int bidx = blockIdx.x;
    int pair = bidx >> 4, q = bidx & 15;
    int d = threadIdx.x;
    int hg = q >> 2, t = q & 3;
    int b = pair >> 2, kvh = pair & 3;

    float ms[NSPLITS];
    float M = -3.0e38f;
#pragma unroll
    for (int i = 0; i < NSPLITS; i++) {
        ms[i] = g_pm[(pair * NSPLITS + i) * 16 + q];
        M = fmaxf(M, ms[i]);
    }
    float L = 0.f, acc = 0.f;
#pragma unroll
    for (int i = 0; i < NSPLITS; i++) {
        float wgt = __expf(ms[i] - M);
        L += wgt * g_pl[(pair * NSPLITS + i) * 16 + q];
        acc += wgt * g_po[((size_t)(pair * NSPLITS + i) * 16 + q) * 128 + d];
    }
    g_y[(b * 4 + t) * 2048 + (kvh * 4 + hg) * 128 + d] = acc / L;
}

// ---------------------------------------------------------------------------
__global__ void reduce_out_kernel(float* __restrict__ out) {
    int gid = blockIdx.x * 256 + threadIdx.x;
    if (gid >= 64 * 2048 / 4) return;
    const float4* P = (const float4*)&g_out_part[0][0][0];
    float4 s = make_float4(0.f, 0.f, 0.f, 0.f);
#pragma unroll
    for (int ks = 0; ks < PROJ_KS; ks++) {
        float4 v = P[(size_t)ks * 32768 + gid];
        s.x += v.x; s.y += v.y; s.z += v.z; s.w += v.w;
    }
    ((float4*)out)[gid] = s;
}

// ---------------------------------------------------------------------------
extern "C" void kernel_launch(void* const* d_in, const int* in_sizes, int n_in,
                              void* d_out, int out_size) {
    const float* x     = (const float*)d_in[0];
    const float* ck    = (const float*)d_in[1];
    const float* cv    = (const float*)d_in[2];
    const float* wq    = (const float*)d_in[3];
    const float* wk    = (const float*)d_in[4];
    const float* wv    = (const float*)d_in[5];
    const float* wproj = (const float*)d_in[6];
    const int*   sp    = (const int*)d_in[7];
    float* out = (float*)d_out;

    float *qkvp, *yp, *outp;
    cudaGetSymbolAddress((void**)&qkvp, g_qkv_part);
    cudaGetSymbolAddress((void**)&yp, g_y);
    cudaGetSymbolAddress((void**)&outp, g_out_part);

    cudaFuncSetAttribute(attn_kernel,
                         cudaFuncAttributeMaxDynamicSharedMemorySize,
                         ATTN_SMEM_BYTES);

    rope_table_kernel<<<8, 32>>>(sp);
    gemm_tf32<<<dim3(24, QKV_KS), 256>>>(x, wq, wk, wv, qkvp, 3072, 1, 4);
    reduce_rope_kernel<<<384, 256>>>();
    attn_kernel<<<64 * NSPLITS, 256, ATTN_SMEM_BYTES>>>(ck, cv);
    combine_kernel<<<1024, 128>>>();
    gemm_tf32<<<dim3(16, PROJ_KS), 256>>>(yp, wproj, wproj, wproj, outp, 2048, 0, 4);
    reduce_out_kernel<<<128, 256>>>(out);
}